// round 2
// baseline (speedup 1.0000x reference)
#include <cuda_runtime.h>
#include <cuda_bf16.h>
#include <cstdint>
#include <cstdio>

// Problem constants
#define NROWS 32768        // B*T
#define PDIM  512
#define NC    8
#define CS    256
#define HD    256
#define TOT   2048         // NC*CS
#define SELF_OUT 1792
#define SELF_IN  1792
#define LN_EPS 1e-5f

// ---------------- device scratch (allocation-free rule) ----------------
__device__ __nv_bfloat16 g_predb[(size_t)NROWS * PDIM];        // 32 MB
__device__ __nv_bfloat16 g_W1b[(size_t)TOT * PDIM];            // 2 MB
__device__ __nv_bfloat16 g_W2b[(size_t)CS * TOT];              // 1 MB (only rows 0..255 of W2 matter)
__device__ __nv_bfloat16 g_LTb[(size_t)CS * SELF_OUT];         // 0.92 MB  LT[v][o] = linear_self[o][v]
__device__ __nv_bfloat16 g_hidden[(size_t)NROWS * TOT];        // 128 MB (pre-LN hidden, no bias/self yet)
__device__ __nv_bfloat16 g_h[(size_t)NROWS * TOT];             // 128 MB (post-LN activations)
__device__ double g_acc;
__device__ int    g_cnt;

// ---------------- helpers ----------------
__device__ __forceinline__ void cp_async16(void* sdst, const void* gsrc) {
    uint32_t s = (uint32_t)__cvta_generic_to_shared(sdst);
    asm volatile("cp.async.cg.shared.global [%0], [%1], 16;\n" :: "r"(s), "l"(gsrc));
}
__device__ __forceinline__ void cp_commit() { asm volatile("cp.async.commit_group;\n"); }

__device__ __forceinline__ void mma16816(float* c, const uint32_t* a, const uint32_t* b) {
    asm volatile(
        "mma.sync.aligned.m16n8k16.row.col.f32.bf16.bf16.f32 "
        "{%0,%1,%2,%3}, {%4,%5,%6,%7}, {%8,%9}, {%0,%1,%2,%3};\n"
        : "+f"(c[0]), "+f"(c[1]), "+f"(c[2]), "+f"(c[3])
        : "r"(a[0]), "r"(a[1]), "r"(a[2]), "r"(a[3]), "r"(b[0]), "r"(b[1]));
}

// ---------------- small prep kernels ----------------
__global__ void zero_kernel() { g_acc = 0.0; g_cnt = 0; }

__global__ void cvt_pred_kernel(const float* __restrict__ p) {
    size_t i = (size_t)blockIdx.x * blockDim.x + threadIdx.x;
    size_t stride = (size_t)gridDim.x * blockDim.x;
    const size_t n = (size_t)NROWS * PDIM;
    for (; i < n; i += stride) g_predb[i] = __float2bfloat16_rn(p[i]);
}
__global__ void cvt_w1_kernel(const float* __restrict__ p) {
    size_t i = (size_t)blockIdx.x * blockDim.x + threadIdx.x;
    size_t stride = (size_t)gridDim.x * blockDim.x;
    const size_t n = (size_t)TOT * PDIM;
    for (; i < n; i += stride) g_W1b[i] = __float2bfloat16_rn(p[i]);
}
__global__ void cvt_w2_kernel(const float* __restrict__ p) {
    size_t i = (size_t)blockIdx.x * blockDim.x + threadIdx.x;
    size_t stride = (size_t)gridDim.x * blockDim.x;
    const size_t n = (size_t)CS * TOT;   // first 256 rows of W2
    for (; i < n; i += stride) g_W2b[i] = __float2bfloat16_rn(p[i]);
}

// LT[v][o] = linear_self[o][v], v in [0,256), o in [0,1792)
__global__ void transpose_lt_kernel(const float* __restrict__ ls) {
    __shared__ float t[32][33];
    int o0 = blockIdx.x * 32, v0 = blockIdx.y * 32;
    int tx = threadIdx.x, ty = threadIdx.y; // 32 x 8
    #pragma unroll
    for (int k = 0; k < 32; k += 8)
        t[ty + k][tx] = ls[(size_t)(o0 + ty + k) * SELF_IN + (v0 + tx)];
    __syncthreads();
    #pragma unroll
    for (int k = 0; k < 32; k += 8)
        g_LTb[(size_t)(v0 + ty + k) * SELF_OUT + (o0 + tx)] = __float2bfloat16_rn(t[tx][ty + k]);
}

__global__ void count_kernel(const int* __restrict__ idx) {
    int i = blockIdx.x * blockDim.x + threadIdx.x;   // grid sized exactly N*NC
    int v = (idx[i] >= 0) ? 1 : 0;
    #pragma unroll
    for (int off = 16; off; off >>= 1) v += __shfl_xor_sync(0xffffffffu, v, off);
    if ((threadIdx.x & 31) == 0) atomicAdd(&g_cnt, v);
}

__global__ void finalize_kernel(float* out, int out_size) {
    out[0] = (float)g_acc;
    if (out_size > 1) out[1] = (float)g_cnt;
}

// ---------------- GEMM1: hidden[32768,2048] = pred[32768,512] @ W1^T ----------------
// BM=128 BN=128 BK=32, 256 threads (8 warps as 4m x 2n, warp tile 32x64)
__global__ __launch_bounds__(256) void gemm1_kernel() {
    const int tid = threadIdx.x, lane = tid & 31, wid = tid >> 5;
    const int wm = wid & 3, wn = wid >> 2;
    const int m0 = blockIdx.y * 128, n0 = blockIdx.x * 128;

    __shared__ __nv_bfloat16 As[2][128 * 40];
    __shared__ __nv_bfloat16 Bs[2][128 * 40];

    float acc[2][8][4];
    #pragma unroll
    for (int a = 0; a < 2; a++)
        #pragma unroll
        for (int b = 0; b < 8; b++)
            #pragma unroll
            for (int c = 0; c < 4; c++) acc[a][b][c] = 0.f;

    const __nv_bfloat16* Ag = g_predb + (size_t)m0 * PDIM;
    const __nv_bfloat16* Bg = g_W1b + (size_t)n0 * PDIM;

    const int r_ld0 = tid >> 2, c_ld0 = (tid & 3) * 8;      // chunk 0
    const int r_ld1 = (tid + 256) >> 2, c_ld1 = ((tid + 256) & 3) * 8;

    // prefetch kt=0
    {
        cp_async16(&As[0][r_ld0 * 40 + c_ld0], Ag + (size_t)r_ld0 * PDIM + c_ld0);
        cp_async16(&Bs[0][r_ld0 * 40 + c_ld0], Bg + (size_t)r_ld0 * PDIM + c_ld0);
        cp_async16(&As[0][r_ld1 * 40 + c_ld1], Ag + (size_t)r_ld1 * PDIM + c_ld1);
        cp_async16(&Bs[0][r_ld1 * 40 + c_ld1], Bg + (size_t)r_ld1 * PDIM + c_ld1);
        cp_commit();
    }

    const int KT = PDIM / 32; // 16
    for (int kt = 0; kt < KT; kt++) {
        int buf = kt & 1;
        if (kt + 1 < KT) {
            int k0 = (kt + 1) * 32;
            cp_async16(&As[buf ^ 1][r_ld0 * 40 + c_ld0], Ag + (size_t)r_ld0 * PDIM + k0 + c_ld0);
            cp_async16(&Bs[buf ^ 1][r_ld0 * 40 + c_ld0], Bg + (size_t)r_ld0 * PDIM + k0 + c_ld0);
            cp_async16(&As[buf ^ 1][r_ld1 * 40 + c_ld1], Ag + (size_t)r_ld1 * PDIM + k0 + c_ld1);
            cp_async16(&Bs[buf ^ 1][r_ld1 * 40 + c_ld1], Bg + (size_t)r_ld1 * PDIM + k0 + c_ld1);
            cp_commit();
            asm volatile("cp.async.wait_group 1;\n");
        } else {
            asm volatile("cp.async.wait_group 0;\n");
        }
        __syncthreads();

        const __nv_bfloat16* Asb = As[buf];
        const __nv_bfloat16* Bsb = Bs[buf];
        #pragma unroll
        for (int ks = 0; ks < 32; ks += 16) {
            uint32_t a[2][4], b[8][2];
            int ar = wm * 32 + (lane >> 2);
            int ac = ks + (lane & 3) * 2;
            #pragma unroll
            for (int mi = 0; mi < 2; mi++) {
                int base = (ar + mi * 16) * 40 + ac;
                a[mi][0] = *(const uint32_t*)(Asb + base);
                a[mi][1] = *(const uint32_t*)(Asb + base + 8 * 40);
                a[mi][2] = *(const uint32_t*)(Asb + base + 8);
                a[mi][3] = *(const uint32_t*)(Asb + base + 8 * 40 + 8);
            }
            int bn = wn * 64 + (lane >> 2);
            int bk = ks + (lane & 3) * 2;
            #pragma unroll
            for (int ni = 0; ni < 8; ni++) {
                int base = (bn + ni * 8) * 40 + bk;
                b[ni][0] = *(const uint32_t*)(Bsb + base);
                b[ni][1] = *(const uint32_t*)(Bsb + base + 8);
            }
            #pragma unroll
            for (int mi = 0; mi < 2; mi++)
                #pragma unroll
                for (int ni = 0; ni < 8; ni++)
                    mma16816(acc[mi][ni], a[mi], b[ni]);
        }
        __syncthreads();
    }

    // epilogue: store bf16 hidden
    __nv_bfloat162* H2 = reinterpret_cast<__nv_bfloat162*>(g_hidden);
    int r0 = m0 + wm * 32 + (lane >> 2);
    int c0 = n0 + wn * 64 + (lane & 3) * 2;
    #pragma unroll
    for (int mi = 0; mi < 2; mi++) {
        #pragma unroll
        for (int ni = 0; ni < 8; ni++) {
            int r = r0 + mi * 16;
            int c = c0 + ni * 8;
            H2[((size_t)r * TOT + c) >> 1] = __floats2bfloat162_rn(acc[mi][ni][0], acc[mi][ni][1]);
            H2[((size_t)(r + 8) * TOT + c) >> 1] = __floats2bfloat162_rn(acc[mi][ni][2], acc[mi][ni][3]);
        }
    }
}

// ---------------- LN kernel: h = LN(relu(hidden + b1 + self)) ----------------
__global__ __launch_bounds__(256) void ln_kernel(const int* __restrict__ idx,
                                                 const float* __restrict__ b1,
                                                 const float* __restrict__ gamma,
                                                 const float* __restrict__ beta) {
    const int n = blockIdx.x;
    const int tid = threadIdx.x, lane = tid & 31, wid = tid >> 5;
    __shared__ int sidx[8];
    __shared__ float sS[8], sS2[8];

    if (tid < 8) {
        int v = idx[(size_t)n * NC + tid];
        bool dup = false;
        for (int j = 0; j < tid; j++)
            if (idx[(size_t)n * NC + j] == v) dup = true;
        sidx[tid] = (v >= 0 && v < CS && !dup) ? v : -1;
    }
    __syncthreads();

    float v[8];
    float s = 0.f, s2 = 0.f;
    #pragma unroll
    for (int i = 0; i < 8; i++) {
        int c = tid + i * 256;
        float x = __bfloat162float(g_hidden[(size_t)n * TOT + c]) + b1[c];
        if (i >= 1) {
            int o = c - CS;
            #pragma unroll
            for (int j = 0; j < 8; j++) {
                int vv = sidx[j];
                if (vv >= 0) x += __bfloat162float(g_LTb[(size_t)vv * SELF_OUT + o]);
            }
        }
        x = fmaxf(x, 0.f);
        v[i] = x; s += x; s2 += x * x;
    }
    #pragma unroll
    for (int off = 16; off; off >>= 1) {
        s  += __shfl_xor_sync(0xffffffffu, s, off);
        s2 += __shfl_xor_sync(0xffffffffu, s2, off);
    }
    if (lane == 0) { sS[wid] = s; sS2[wid] = s2; }
    __syncthreads();
    if (tid == 0) {
        float a = 0.f, b = 0.f;
        for (int w = 0; w < 8; w++) { a += sS[w]; b += sS2[w]; }
        sS[0] = a; sS2[0] = b;
    }
    __syncthreads();
    float mu  = sS[0] * (1.f / TOT);
    float var = sS2[0] * (1.f / TOT) - mu * mu;
    float inv = rsqrtf(var + LN_EPS);
    #pragma unroll
    for (int i = 0; i < 8; i++) {
        int c = tid + i * 256;
        float y = (v[i] - mu) * inv * gamma[c] + beta[c];
        g_h[(size_t)n * TOT + c] = __float2bfloat16_rn(y);
    }
}

// ---------------- GEMM2 + log-softmax + gather-reduce ----------------
// BM=64 BN=256(=full group 0) BK=32, 256 threads (8 warps as 2m x 4n, warp tile 32x64)
#define G2_AS_BYTES (2 * 64 * 40 * 2)      // 10240
#define G2_BS_BYTES (2 * 256 * 40 * 2)     // 40960
#define G2_LS_BYTES (64 * 260 * 4)         // 66560
#define G2_DSMEM    (G2_LS_BYTES + 128)    // Ls overlays As/Bs; sred after Ls

__global__ __launch_bounds__(256) void gemm2_kernel(const int* __restrict__ idx,
                                                    const float* __restrict__ b2) {
    extern __shared__ char dsm[];
    __nv_bfloat16* As = (__nv_bfloat16*)dsm;
    __nv_bfloat16* Bs = (__nv_bfloat16*)(dsm + G2_AS_BYTES);
    float* Ls = (float*)dsm;                       // epilogue reuse
    float* sred = (float*)(dsm + G2_LS_BYTES);

    const int tid = threadIdx.x, lane = tid & 31, wid = tid >> 5;
    const int wm = wid & 1, wn = wid >> 1;
    const int m0 = blockIdx.x * 64;

    float acc[2][8][4];
    #pragma unroll
    for (int a = 0; a < 2; a++)
        #pragma unroll
        for (int b = 0; b < 8; b++)
            #pragma unroll
            for (int c = 0; c < 4; c++) acc[a][b][c] = 0.f;

    const __nv_bfloat16* Ag = g_h + (size_t)m0 * TOT;
    const __nv_bfloat16* Bg = g_W2b;

    const int ar_ld = tid >> 2, ac_ld = (tid & 3) * 8;   // A: 1 chunk/thread
    // B: 4 chunks/thread
    auto load_tile = [&](int kt, int buf) {
        int k0 = kt * 32;
        cp_async16(&As[buf * 64 * 40 + ar_ld * 40 + ac_ld], Ag + (size_t)ar_ld * TOT + k0 + ac_ld);
        #pragma unroll
        for (int it = 0; it < 4; it++) {
            int ch = tid + it * 256;
            int row = ch >> 2, c8 = (ch & 3) * 8;
            cp_async16(&Bs[buf * 256 * 40 + row * 40 + c8], Bg + (size_t)row * TOT + k0 + c8);
        }
        cp_commit();
    };

    load_tile(0, 0);
    const int KT = TOT / 32;  // 64
    for (int kt = 0; kt < KT; kt++) {
        int buf = kt & 1;
        if (kt + 1 < KT) {
            load_tile(kt + 1, buf ^ 1);
            asm volatile("cp.async.wait_group 1;\n");
        } else {
            asm volatile("cp.async.wait_group 0;\n");
        }
        __syncthreads();

        const __nv_bfloat16* Asb = As + buf * 64 * 40;
        const __nv_bfloat16* Bsb = Bs + buf * 256 * 40;
        #pragma unroll
        for (int ks = 0; ks < 32; ks += 16) {
            uint32_t a[2][4], b[8][2];
            int ar = wm * 32 + (lane >> 2);
            int ac = ks + (lane & 3) * 2;
            #pragma unroll
            for (int mi = 0; mi < 2; mi++) {
                int base = (ar + mi * 16) * 40 + ac;
                a[mi][0] = *(const uint32_t*)(Asb + base);
                a[mi][1] = *(const uint32_t*)(Asb + base + 8 * 40);
                a[mi][2] = *(const uint32_t*)(Asb + base + 8);
                a[mi][3] = *(const uint32_t*)(Asb + base + 8 * 40 + 8);
            }
            int bn = wn * 64 + (lane >> 2);
            int bk = ks + (lane & 3) * 2;
            #pragma unroll
            for (int ni = 0; ni < 8; ni++) {
                int base = (bn + ni * 8) * 40 + bk;
                b[ni][0] = *(const uint32_t*)(Bsb + base);
                b[ni][1] = *(const uint32_t*)(Bsb + base + 8);
            }
            #pragma unroll
            for (int mi = 0; mi < 2; mi++)
                #pragma unroll
                for (int ni = 0; ni < 8; ni++)
                    mma16816(acc[mi][ni], a[mi], b[ni]);
        }
        __syncthreads();
    }

    // stage logits (+b2) into smem: Ls[64][260]
    {
        int r0 = wm * 32 + (lane >> 2);
        int c0 = wn * 64 + (lane & 3) * 2;
        #pragma unroll
        for (int mi = 0; mi < 2; mi++) {
            #pragma unroll
            for (int ni = 0; ni < 8; ni++) {
                int r = r0 + mi * 16;
                int c = c0 + ni * 8;
                Ls[r * 260 + c]           = acc[mi][ni][0] + b2[c];
                Ls[r * 260 + c + 1]       = acc[mi][ni][1] + b2[c + 1];
                Ls[(r + 8) * 260 + c]     = acc[mi][ni][2] + b2[c];
                Ls[(r + 8) * 260 + c + 1] = acc[mi][ni][3] + b2[c + 1];
            }
        }
    }
    __syncthreads();

    // per-row logsumexp + gather (4 threads per row)
    int row = tid >> 2, sub = tid & 3;
    const float* Lr = Ls + row * 260;
    float m = -1e30f;
    #pragma unroll 8
    for (int c = sub * 64; c < sub * 64 + 64; c++) m = fmaxf(m, Lr[c]);
    m = fmaxf(m, __shfl_xor_sync(0xffffffffu, m, 1));
    m = fmaxf(m, __shfl_xor_sync(0xffffffffu, m, 2));
    float se = 0.f;
    #pragma unroll 8
    for (int c = sub * 64; c < sub * 64 + 64; c++) se += expf(Lr[c] - m);
    se += __shfl_xor_sync(0xffffffffu, se, 1);
    se += __shfl_xor_sync(0xffffffffu, se, 2);
    float lse = m + logf(se);

    float contrib = 0.f;
    if (sub == 0) {
        int gn = m0 + row;
        int vals[8];
        #pragma unroll
        for (int j = 0; j < 8; j++) vals[j] = idx[(size_t)gn * NC + j];
        float a = 0.f; int cnt = 0;
        #pragma unroll
        for (int j = 0; j < 8; j++) {
            int vv = vals[j];
            if (vv < 0 || vv >= CS) continue;
            bool dup = false;
            for (int j2 = 0; j2 < j; j2++)
                if (vals[j2] == vv) dup = true;
            if (dup) continue;
            a += Lr[vv]; cnt++;
        }
        contrib = a - (float)cnt * lse;
    }
    #pragma unroll
    for (int off = 16; off; off >>= 1) contrib += __shfl_xor_sync(0xffffffffu, contrib, off);
    if (lane == 0) sred[wid] = contrib;
    __syncthreads();
    if (tid == 0) {
        float t = 0.f;
        for (int w = 0; w < 8; w++) t += sred[w];
        atomicAdd(&g_acc, (double)t);
    }
}

// ---------------- launcher ----------------
extern "C" void kernel_launch(void* const* d_in, const int* in_sizes, int n_in,
                              void* d_out, int out_size) {
    const float* pred  = (const float*)d_in[0];
    const int*   idx   = (const int*)  d_in[1];
    const float* W1    = (const float*)d_in[2];
    const float* b1    = (const float*)d_in[3];
    const float* ls    = (const float*)d_in[4];
    const float* gamma = (const float*)d_in[5];
    const float* beta  = (const float*)d_in[6];
    const float* W2    = (const float*)d_in[7];
    const float* b2    = (const float*)d_in[8];
    float* out = (float*)d_out;

    cudaFuncSetAttribute(gemm2_kernel, cudaFuncAttributeMaxDynamicSharedMemorySize, G2_DSMEM);

    zero_kernel<<<1, 1>>>();
    cvt_pred_kernel<<<4096, 256>>>(pred);
    cvt_w1_kernel<<<1024, 256>>>(W1);
    cvt_w2_kernel<<<512, 256>>>(W2);
    transpose_lt_kernel<<<dim3(SELF_OUT / 32, CS / 32), dim3(32, 8)>>>(ls);
    count_kernel<<<(NROWS * NC) / 256, 256>>>(idx);

    gemm1_kernel<<<dim3(TOT / 128, NROWS / 128), 256>>>();
    ln_kernel<<<NROWS, 256>>>(idx, b1, gamma, beta);
    gemm2_kernel<<<NROWS / 64, 256, G2_DSMEM>>>(idx, b2);

    finalize_kernel<<<1, 1>>>(out, out_size);
}

// round 3
// speedup vs baseline: 1.0086x; 1.0086x over previous
#include <cuda_runtime.h>
#include <cuda_bf16.h>
#include <cstdint>
#include <cstdio>

// Problem constants
#define NROWS 32768        // B*T
#define PDIM  512
#define NC    8
#define CS    256
#define HD    256
#define TOT   2048         // NC*CS
#define SELF_OUT 1792
#define SELF_IN  1792
#define LN_EPS 1e-5f

// ---------------- device scratch (allocation-free rule) ----------------
__device__ __nv_bfloat16 g_predb[(size_t)NROWS * PDIM];        // 32 MB
__device__ __nv_bfloat16 g_W1b[(size_t)TOT * PDIM];            // 2 MB
__device__ __nv_bfloat16 g_W2b[(size_t)CS * TOT];              // 1 MB  W2g = W2[0:256]*gamma
__device__ __nv_bfloat16 g_LTb[(size_t)CS * SELF_OUT];         // 0.92 MB  LT[v][o] = linear_self[o][v]
__device__ __nv_bfloat16 g_hidden[(size_t)NROWS * TOT];        // 128 MB (post-relu x)
__device__ float g_s[NROWS], g_s2[NROWS];
__device__ float g_inv[NROWS], g_muinv[NROWS];
__device__ float g_G[CS], g_Bt2[CS];
__device__ double g_acc;
__device__ int    g_cnt;

// ---------------- helpers ----------------
__device__ __forceinline__ void cp_async16(void* sdst, const void* gsrc) {
    uint32_t s = (uint32_t)__cvta_generic_to_shared(sdst);
    asm volatile("cp.async.cg.shared.global [%0], [%1], 16;\n" :: "r"(s), "l"(gsrc));
}
__device__ __forceinline__ void cp_commit() { asm volatile("cp.async.commit_group;\n"); }

__device__ __forceinline__ void mma16816(float* c, const uint32_t* a, const uint32_t* b) {
    asm volatile(
        "mma.sync.aligned.m16n8k16.row.col.f32.bf16.bf16.f32 "
        "{%0,%1,%2,%3}, {%4,%5,%6,%7}, {%8,%9}, {%0,%1,%2,%3};\n"
        : "+f"(c[0]), "+f"(c[1]), "+f"(c[2]), "+f"(c[3])
        : "r"(a[0]), "r"(a[1]), "r"(a[2]), "r"(a[3]), "r"(b[0]), "r"(b[1]));
}

// ---------------- small prep kernels ----------------
__global__ void zero_kernel() { g_acc = 0.0; g_cnt = 0; }

__global__ void clear_stats_kernel() {
    int i = blockIdx.x * blockDim.x + threadIdx.x;
    if (i < NROWS) { g_s[i] = 0.f; g_s2[i] = 0.f; }
}

__global__ void cvt_pred_kernel(const float* __restrict__ p) {
    size_t i = (size_t)blockIdx.x * blockDim.x + threadIdx.x;
    size_t stride = (size_t)gridDim.x * blockDim.x;
    const size_t n = (size_t)NROWS * PDIM;
    for (; i < n; i += stride) g_predb[i] = __float2bfloat16_rn(p[i]);
}
__global__ void cvt_w1_kernel(const float* __restrict__ p) {
    size_t i = (size_t)blockIdx.x * blockDim.x + threadIdx.x;
    size_t stride = (size_t)gridDim.x * blockDim.x;
    const size_t n = (size_t)TOT * PDIM;
    for (; i < n; i += stride) g_W1b[i] = __float2bfloat16_rn(p[i]);
}
// W2g = W2[0:256] * gamma (broadcast over columns)
__global__ void cvt_w2_kernel(const float* __restrict__ p, const float* __restrict__ gamma) {
    size_t i = (size_t)blockIdx.x * blockDim.x + threadIdx.x;
    size_t stride = (size_t)gridDim.x * blockDim.x;
    const size_t n = (size_t)CS * TOT;
    for (; i < n; i += stride) {
        int c = (int)(i & (TOT - 1));
        g_W2b[i] = __float2bfloat16_rn(p[i] * gamma[c]);
    }
}

// G[j] = sum_c gamma[c]*W2[j,c] ; Bt2[j] = sum_c beta[c]*W2[j,c] + b2[j]
__global__ void gb_kernel(const float* __restrict__ W2, const float* __restrict__ gamma,
                          const float* __restrict__ beta, const float* __restrict__ b2) {
    int j = blockIdx.x;
    int tid = threadIdx.x, lane = tid & 31, wid = tid >> 5;
    __shared__ float sg[8], sb[8];
    float ag = 0.f, ab = 0.f;
    for (int c = tid; c < TOT; c += 256) {
        float w = W2[(size_t)j * TOT + c];
        ag += gamma[c] * w;
        ab += beta[c] * w;
    }
    #pragma unroll
    for (int off = 16; off; off >>= 1) {
        ag += __shfl_xor_sync(0xffffffffu, ag, off);
        ab += __shfl_xor_sync(0xffffffffu, ab, off);
    }
    if (lane == 0) { sg[wid] = ag; sb[wid] = ab; }
    __syncthreads();
    if (tid == 0) {
        float a = 0.f, b = 0.f;
        for (int w = 0; w < 8; w++) { a += sg[w]; b += sb[w]; }
        g_G[j] = a; g_Bt2[j] = b + b2[j];
    }
}

// LT[v][o] = linear_self[o][v], v in [0,256), o in [0,1792)
__global__ void transpose_lt_kernel(const float* __restrict__ ls) {
    __shared__ float t[32][33];
    int o0 = blockIdx.x * 32, v0 = blockIdx.y * 32;
    int tx = threadIdx.x, ty = threadIdx.y; // 32 x 8
    #pragma unroll
    for (int k = 0; k < 32; k += 8)
        t[ty + k][tx] = ls[(size_t)(o0 + ty + k) * SELF_IN + (v0 + tx)];
    __syncthreads();
    #pragma unroll
    for (int k = 0; k < 32; k += 8)
        g_LTb[(size_t)(v0 + ty + k) * SELF_OUT + (o0 + tx)] = __float2bfloat16_rn(t[tx][ty + k]);
}

__global__ void count_kernel(const int* __restrict__ idx) {
    int i = blockIdx.x * blockDim.x + threadIdx.x;
    int v = (idx[i] >= 0) ? 1 : 0;
    #pragma unroll
    for (int off = 16; off; off >>= 1) v += __shfl_xor_sync(0xffffffffu, v, off);
    if ((threadIdx.x & 31) == 0) atomicAdd(&g_cnt, v);
}

__global__ void stats_kernel() {
    int r = blockIdx.x * blockDim.x + threadIdx.x;
    if (r < NROWS) {
        float mu  = g_s[r] * (1.f / TOT);
        float var = g_s2[r] * (1.f / TOT) - mu * mu;
        float inv = rsqrtf(var + LN_EPS);
        g_inv[r] = inv;
        g_muinv[r] = mu * inv;
    }
}

__global__ void finalize_kernel(float* out, int out_size) {
    out[0] = (float)g_acc;
    if (out_size > 1) out[1] = (float)g_cnt;
}

// ---------------- GEMM1 fused: x = relu(pred@W1^T + b1 + self), stats ----------------
// BM=128 BN=128 BK=32, 256 threads (8 warps as 4m x 2n, warp tile 32x64)
#define G1_PIPE_BYTES (2 * 128 * 40 * 2 * 2)     // As + Bs double-buffered = 40960
#define G1_LTS_STRIDE 136
#define G1_LTS_BYTES  (CS * G1_LTS_STRIDE * 2)   // 69632
#define G1_DSMEM      (G1_LTS_BYTES + 128 * 8 * 4)  // + sidx = 73728

__global__ __launch_bounds__(256) void gemm1_kernel(const int* __restrict__ idx,
                                                    const float* __restrict__ b1) {
    extern __shared__ char dyn1[];
    __nv_bfloat16* As = (__nv_bfloat16*)dyn1;                  // [2][128*40]
    __nv_bfloat16* Bs = As + 2 * 128 * 40;                     // [2][128*40]
    __nv_bfloat16* LTs = (__nv_bfloat16*)dyn1;                 // epilogue overlay [256][136]
    int* sidx = (int*)(dyn1 + G1_LTS_BYTES);                   // [128][8]

    const int tid = threadIdx.x, lane = tid & 31, wid = tid >> 5;
    const int wm = wid & 3, wn = wid >> 2;
    const int m0 = blockIdx.y * 128, n0 = blockIdx.x * 128;

    float acc[2][8][4];
    #pragma unroll
    for (int a = 0; a < 2; a++)
        #pragma unroll
        for (int b = 0; b < 8; b++)
            #pragma unroll
            for (int c = 0; c < 4; c++) acc[a][b][c] = 0.f;

    const __nv_bfloat16* Ag = g_predb + (size_t)m0 * PDIM;
    const __nv_bfloat16* Bg = g_W1b + (size_t)n0 * PDIM;

    const int r_ld0 = tid >> 2, c_ld0 = (tid & 3) * 8;
    const int r_ld1 = (tid + 256) >> 2, c_ld1 = ((tid + 256) & 3) * 8;

    {
        cp_async16(&As[r_ld0 * 40 + c_ld0], Ag + (size_t)r_ld0 * PDIM + c_ld0);
        cp_async16(&Bs[r_ld0 * 40 + c_ld0], Bg + (size_t)r_ld0 * PDIM + c_ld0);
        cp_async16(&As[r_ld1 * 40 + c_ld1], Ag + (size_t)r_ld1 * PDIM + c_ld1);
        cp_async16(&Bs[r_ld1 * 40 + c_ld1], Bg + (size_t)r_ld1 * PDIM + c_ld1);
        cp_commit();
    }

    const int KT = PDIM / 32; // 16
    for (int kt = 0; kt < KT; kt++) {
        int buf = kt & 1;
        if (kt + 1 < KT) {
            int k0 = (kt + 1) * 32;
            int nb = (buf ^ 1) * 128 * 40;
            cp_async16(&As[nb + r_ld0 * 40 + c_ld0], Ag + (size_t)r_ld0 * PDIM + k0 + c_ld0);
            cp_async16(&Bs[nb + r_ld0 * 40 + c_ld0], Bg + (size_t)r_ld0 * PDIM + k0 + c_ld0);
            cp_async16(&As[nb + r_ld1 * 40 + c_ld1], Ag + (size_t)r_ld1 * PDIM + k0 + c_ld1);
            cp_async16(&Bs[nb + r_ld1 * 40 + c_ld1], Bg + (size_t)r_ld1 * PDIM + k0 + c_ld1);
            cp_commit();
            asm volatile("cp.async.wait_group 1;\n");
        } else {
            asm volatile("cp.async.wait_group 0;\n");
        }
        __syncthreads();

        const __nv_bfloat16* Asb = As + buf * 128 * 40;
        const __nv_bfloat16* Bsb = Bs + buf * 128 * 40;
        #pragma unroll
        for (int ks = 0; ks < 32; ks += 16) {
            uint32_t a[2][4], b[8][2];
            int ar = wm * 32 + (lane >> 2);
            int ac = ks + (lane & 3) * 2;
            #pragma unroll
            for (int mi = 0; mi < 2; mi++) {
                int base = (ar + mi * 16) * 40 + ac;
                a[mi][0] = *(const uint32_t*)(Asb + base);
                a[mi][1] = *(const uint32_t*)(Asb + base + 8 * 40);
                a[mi][2] = *(const uint32_t*)(Asb + base + 8);
                a[mi][3] = *(const uint32_t*)(Asb + base + 8 * 40 + 8);
            }
            int bn = wn * 64 + (lane >> 2);
            int bk = ks + (lane & 3) * 2;
            #pragma unroll
            for (int ni = 0; ni < 8; ni++) {
                int base = (bn + ni * 8) * 40 + bk;
                b[ni][0] = *(const uint32_t*)(Bsb + base);
                b[ni][1] = *(const uint32_t*)(Bsb + base + 8);
            }
            #pragma unroll
            for (int mi = 0; mi < 2; mi++)
                #pragma unroll
                for (int ni = 0; ni < 8; ni++)
                    mma16816(acc[mi][ni], a[mi], b[ni]);
        }
        __syncthreads();
    }

    // -------- fused epilogue: + b1 + self, relu, stats, store bf16 x --------
    const bool has_self = (n0 >= CS);

    if (tid < 128) {
        int vals[8];
        #pragma unroll
        for (int j = 0; j < 8; j++) vals[j] = idx[(size_t)(m0 + tid) * NC + j];
        #pragma unroll
        for (int j = 0; j < 8; j++) {
            int v = vals[j];
            bool dup = false;
            for (int j2 = 0; j2 < j; j2++)
                if (vals[j2] == v) dup = true;
            sidx[tid * 8 + j] = (v >= 0 && v < CS && !dup) ? v : -1;
        }
    }
    if (has_self) {
        int o0 = n0 - CS;
        #pragma unroll
        for (int it = 0; it < 16; it++) {
            int ch = tid + it * 256;
            int v = ch >> 4, c8 = (ch & 15) * 8;
            *(uint4*)&LTs[v * G1_LTS_STRIDE + c8] =
                *(const uint4*)&g_LTb[(size_t)v * SELF_OUT + o0 + c8];
        }
    }
    __syncthreads();

    const int lr = lane >> 2, lc = (lane & 3) * 2;
    #pragma unroll
    for (int mi = 0; mi < 2; mi++) {
        #pragma unroll
        for (int h = 0; h < 2; h++) {
            int rloc = wm * 32 + lr + mi * 16 + h * 8;
            int rglob = m0 + rloc;
            int vs[8];
            #pragma unroll
            for (int j = 0; j < 8; j++) vs[j] = sidx[rloc * 8 + j];
            float s = 0.f, s2 = 0.f;
            #pragma unroll
            for (int ni = 0; ni < 8; ni++) {
                int cl = wn * 64 + ni * 8 + lc;
                int cg = n0 + cl;
                float x0 = acc[mi][ni][h * 2]     + __ldg(&b1[cg]);
                float x1 = acc[mi][ni][h * 2 + 1] + __ldg(&b1[cg + 1]);
                if (has_self) {
                    #pragma unroll
                    for (int j = 0; j < 8; j++) {
                        int v = vs[j];
                        if (v >= 0) {
                            __nv_bfloat162 p = *(const __nv_bfloat162*)&LTs[v * G1_LTS_STRIDE + cl];
                            x0 += __bfloat162float(p.x);
                            x1 += __bfloat162float(p.y);
                        }
                    }
                }
                x0 = fmaxf(x0, 0.f); x1 = fmaxf(x1, 0.f);
                s += x0 + x1; s2 += x0 * x0 + x1 * x1;
                *(__nv_bfloat162*)&g_hidden[(size_t)rglob * TOT + cg] = __floats2bfloat162_rn(x0, x1);
            }
            s  += __shfl_xor_sync(0xffffffffu, s, 1);
            s  += __shfl_xor_sync(0xffffffffu, s, 2);
            s2 += __shfl_xor_sync(0xffffffffu, s2, 1);
            s2 += __shfl_xor_sync(0xffffffffu, s2, 2);
            if ((lane & 3) == 0) {
                atomicAdd(&g_s[rglob], s);
                atomicAdd(&g_s2[rglob], s2);
            }
        }
    }
}

// ---------------- GEMM2 + LN-affine fold + log-softmax + gather-reduce ----------------
// BM=64 BN=256 BK=32, 256 threads (8 warps as 2m x 4n, warp tile 32x64)
#define G2_AS_BYTES (2 * 64 * 40 * 2)      // 10240
#define G2_BS_BYTES (2 * 256 * 40 * 2)     // 40960
#define G2_LS_BYTES (64 * 260 * 4)         // 66560
#define G2_DSMEM    (G2_LS_BYTES + 128)

__global__ __launch_bounds__(256) void gemm2_kernel(const int* __restrict__ idx) {
    extern __shared__ char dsm[];
    __nv_bfloat16* As = (__nv_bfloat16*)dsm;
    __nv_bfloat16* Bs = (__nv_bfloat16*)(dsm + G2_AS_BYTES);
    float* Ls = (float*)dsm;                       // epilogue reuse
    float* sred = (float*)(dsm + G2_LS_BYTES);

    const int tid = threadIdx.x, lane = tid & 31, wid = tid >> 5;
    const int wm = wid & 1, wn = wid >> 1;
    const int m0 = blockIdx.x * 64;

    float acc[2][8][4];
    #pragma unroll
    for (int a = 0; a < 2; a++)
        #pragma unroll
        for (int b = 0; b < 8; b++)
            #pragma unroll
            for (int c = 0; c < 4; c++) acc[a][b][c] = 0.f;

    const __nv_bfloat16* Ag = g_hidden + (size_t)m0 * TOT;
    const __nv_bfloat16* Bg = g_W2b;

    const int ar_ld = tid >> 2, ac_ld = (tid & 3) * 8;
    auto load_tile = [&](int kt, int buf) {
        int k0 = kt * 32;
        cp_async16(&As[buf * 64 * 40 + ar_ld * 40 + ac_ld], Ag + (size_t)ar_ld * TOT + k0 + ac_ld);
        #pragma unroll
        for (int it = 0; it < 4; it++) {
            int ch = tid + it * 256;
            int row = ch >> 2, c8 = (ch & 3) * 8;
            cp_async16(&Bs[buf * 256 * 40 + row * 40 + c8], Bg + (size_t)row * TOT + k0 + c8);
        }
        cp_commit();
    };

    load_tile(0, 0);
    const int KT = TOT / 32;  // 64
    for (int kt = 0; kt < KT; kt++) {
        int buf = kt & 1;
        if (kt + 1 < KT) {
            load_tile(kt + 1, buf ^ 1);
            asm volatile("cp.async.wait_group 1;\n");
        } else {
            asm volatile("cp.async.wait_group 0;\n");
        }
        __syncthreads();

        const __nv_bfloat16* Asb = As + buf * 64 * 40;
        const __nv_bfloat16* Bsb = Bs + buf * 256 * 40;
        #pragma unroll
        for (int ks = 0; ks < 32; ks += 16) {
            uint32_t a[2][4], b[8][2];
            int ar = wm * 32 + (lane >> 2);
            int ac = ks + (lane & 3) * 2;
            #pragma unroll
            for (int mi = 0; mi < 2; mi++) {
                int base = (ar + mi * 16) * 40 + ac;
                a[mi][0] = *(const uint32_t*)(Asb + base);
                a[mi][1] = *(const uint32_t*)(Asb + base + 8 * 40);
                a[mi][2] = *(const uint32_t*)(Asb + base + 8);
                a[mi][3] = *(const uint32_t*)(Asb + base + 8 * 40 + 8);
            }
            int bn = wn * 64 + (lane >> 2);
            int bk = ks + (lane & 3) * 2;
            #pragma unroll
            for (int ni = 0; ni < 8; ni++) {
                int base = (bn + ni * 8) * 40 + bk;
                b[ni][0] = *(const uint32_t*)(Bsb + base);
                b[ni][1] = *(const uint32_t*)(Bsb + base + 8);
            }
            #pragma unroll
            for (int mi = 0; mi < 2; mi++)
                #pragma unroll
                for (int ni = 0; ni < 8; ni++)
                    mma16816(acc[mi][ni], a[mi], b[ni]);
        }
        __syncthreads();
    }

    // stage logits into smem with LN affine folded:
    // logit = acc*inv_r - muinv_r*G[c] + Bt2[c]
    {
        int r0 = wm * 32 + (lane >> 2);
        int c0 = wn * 64 + (lane & 3) * 2;
        #pragma unroll
        for (int mi = 0; mi < 2; mi++) {
            #pragma unroll
            for (int h = 0; h < 2; h++) {
                int r = r0 + mi * 16 + h * 8;
                float inv = __ldg(&g_inv[m0 + r]);
                float mui = __ldg(&g_muinv[m0 + r]);
                #pragma unroll
                for (int ni = 0; ni < 8; ni++) {
                    int c = c0 + ni * 8;
                    float g0 = __ldg(&g_G[c]),   g1 = __ldg(&g_G[c + 1]);
                    float t0 = __ldg(&g_Bt2[c]), t1 = __ldg(&g_Bt2[c + 1]);
                    Ls[r * 260 + c]     = acc[mi][ni][h * 2]     * inv - mui * g0 + t0;
                    Ls[r * 260 + c + 1] = acc[mi][ni][h * 2 + 1] * inv - mui * g1 + t1;
                }
            }
        }
    }
    __syncthreads();

    // per-row logsumexp + gather (4 threads per row)
    int row = tid >> 2, sub = tid & 3;
    const float* Lr = Ls + row * 260;
    float m = -1e30f;
    #pragma unroll 8
    for (int c = sub * 64; c < sub * 64 + 64; c++) m = fmaxf(m, Lr[c]);
    m = fmaxf(m, __shfl_xor_sync(0xffffffffu, m, 1));
    m = fmaxf(m, __shfl_xor_sync(0xffffffffu, m, 2));
    float se = 0.f;
    #pragma unroll 8
    for (int c = sub * 64; c < sub * 64 + 64; c++) se += expf(Lr[c] - m);
    se += __shfl_xor_sync(0xffffffffu, se, 1);
    se += __shfl_xor_sync(0xffffffffu, se, 2);
    float lse = m + logf(se);

    float contrib = 0.f;
    if (sub == 0) {
        int gn = m0 + row;
        int vals[8];
        #pragma unroll
        for (int j = 0; j < 8; j++) vals[j] = idx[(size_t)gn * NC + j];
        float a = 0.f; int cnt = 0;
        #pragma unroll
        for (int j = 0; j < 8; j++) {
            int vv = vals[j];
            if (vv < 0 || vv >= CS) continue;
            bool dup = false;
            for (int j2 = 0; j2 < j; j2++)
                if (vals[j2] == vv) dup = true;
            if (dup) continue;
            a += Lr[vv]; cnt++;
        }
        contrib = a - (float)cnt * lse;
    }
    #pragma unroll
    for (int off = 16; off; off >>= 1) contrib += __shfl_xor_sync(0xffffffffu, contrib, off);
    if (lane == 0) sred[wid] = contrib;
    __syncthreads();
    if (tid == 0) {
        float t = 0.f;
        for (int w = 0; w < 8; w++) t += sred[w];
        atomicAdd(&g_acc, (double)t);
    }
}

// ---------------- launcher ----------------
extern "C" void kernel_launch(void* const* d_in, const int* in_sizes, int n_in,
                              void* d_out, int out_size) {
    const float* pred  = (const float*)d_in[0];
    const int*   idx   = (const int*)  d_in[1];
    const float* W1    = (const float*)d_in[2];
    const float* b1    = (const float*)d_in[3];
    const float* ls    = (const float*)d_in[4];
    const float* gamma = (const float*)d_in[5];
    const float* beta  = (const float*)d_in[6];
    const float* W2    = (const float*)d_in[7];
    const float* b2    = (const float*)d_in[8];
    float* out = (float*)d_out;

    cudaFuncSetAttribute(gemm1_kernel, cudaFuncAttributeMaxDynamicSharedMemorySize, G1_DSMEM);
    cudaFuncSetAttribute(gemm2_kernel, cudaFuncAttributeMaxDynamicSharedMemorySize, G2_DSMEM);

    zero_kernel<<<1, 1>>>();
    clear_stats_kernel<<<NROWS / 256, 256>>>();
    cvt_pred_kernel<<<4096, 256>>>(pred);
    cvt_w1_kernel<<<1024, 256>>>(W1);
    cvt_w2_kernel<<<512, 256>>>(W2, gamma);
    transpose_lt_kernel<<<dim3(SELF_OUT / 32, CS / 32), dim3(32, 8)>>>(ls);
    gb_kernel<<<CS, 256>>>(W2, gamma, beta, b2);
    count_kernel<<<(NROWS * NC) / 256, 256>>>(idx);

    gemm1_kernel<<<dim3(TOT / 128, NROWS / 128), 256, G1_DSMEM>>>(idx, b1);
    stats_kernel<<<NROWS / 256, 256>>>();
    gemm2_kernel<<<NROWS / 64, 256, G2_DSMEM>>>(idx);

    finalize_kernel<<<1, 1>>>(out, out_size);
}

// round 9
// speedup vs baseline: 2.0701x; 2.0524x over previous
#include <cuda_runtime.h>
#include <cuda_bf16.h>
#include <cstdint>

// Problem constants
#define NROWS 32768        // B*T
#define PDIM  512
#define NC    8
#define CS    256
#define TOT   2048         // NC*CS
#define SELF_OUT 1792
#define SELF_IN  1792
#define LN_EPS 1e-5f

// ---------------- device scratch (allocation-free rule) ----------------
__device__ __nv_bfloat16 g_predb[(size_t)NROWS * PDIM];        // 32 MB
__device__ __nv_bfloat16 g_W1b[(size_t)TOT * PDIM];            // 2 MB
__device__ __nv_bfloat16 g_W2b[(size_t)CS * TOT];              // 1 MB  W2g = W2[0:256]*gamma
__device__ __nv_bfloat16 g_LTb[(size_t)CS * SELF_OUT];         // LT[v][o] = linear_self[o][v]
__device__ __nv_bfloat16 g_hidden[(size_t)NROWS * TOT];        // 128 MB (post-relu x)
__device__ float g_s[NROWS], g_s2[NROWS];
__device__ float g_inv[NROWS], g_muinv[NROWS];
__device__ float g_G[CS], g_Bt2[CS];
__device__ double g_acc;
__device__ int    g_cnt;

// ---------------- helpers ----------------
__device__ __forceinline__ uint32_t smem_u32(const void* p) {
    uint32_t a;
    asm("{ .reg .u64 t; cvta.to.shared.u64 t, %1; cvt.u32.u64 %0, t; }" : "=r"(a) : "l"(p));
    return a;
}
__device__ __forceinline__ void cp_async16(void* sdst, const void* gsrc) {
    uint32_t s = (uint32_t)__cvta_generic_to_shared(sdst);
    asm volatile("cp.async.cg.shared.global [%0], [%1], 16;\n" :: "r"(s), "l"(gsrc));
}
__device__ __forceinline__ void cp_commit() { asm volatile("cp.async.commit_group;\n"); }

__device__ __forceinline__ void ldsm_x4(uint32_t* r, uint32_t addr) {
    asm volatile("ldmatrix.sync.aligned.m8n8.x4.shared.b16 {%0,%1,%2,%3}, [%4];"
        : "=r"(r[0]), "=r"(r[1]), "=r"(r[2]), "=r"(r[3]) : "r"(addr));
}

__device__ __forceinline__ void mma16816(float* c, const uint32_t* a, const uint32_t* b) {
    asm volatile(
        "mma.sync.aligned.m16n8k16.row.col.f32.bf16.bf16.f32 "
        "{%0,%1,%2,%3}, {%4,%5,%6,%7}, {%8,%9}, {%0,%1,%2,%3};\n"
        : "+f"(c[0]), "+f"(c[1]), "+f"(c[2]), "+f"(c[3])
        : "r"(a[0]), "r"(a[1]), "r"(a[2]), "r"(a[3]), "r"(b[0]), "r"(b[1]));
}

// ---------------- small prep kernels ----------------
__global__ void zero_kernel() { g_acc = 0.0; g_cnt = 0; }

__global__ void clear_stats_kernel() {
    int i = blockIdx.x * blockDim.x + threadIdx.x;
    if (i < NROWS) { g_s[i] = 0.f; g_s2[i] = 0.f; }
}

__global__ void cvt_pred_kernel(const float4* __restrict__ p) {
    size_t i = (size_t)blockIdx.x * blockDim.x + threadIdx.x;
    size_t stride = (size_t)gridDim.x * blockDim.x;
    const size_t n = (size_t)NROWS * PDIM / 4;
    __nv_bfloat162* o = (__nv_bfloat162*)g_predb;
    for (; i < n; i += stride) {
        float4 v = p[i];
        o[2 * i]     = __floats2bfloat162_rn(v.x, v.y);
        o[2 * i + 1] = __floats2bfloat162_rn(v.z, v.w);
    }
}
__global__ void cvt_w1_kernel(const float4* __restrict__ p) {
    size_t i = (size_t)blockIdx.x * blockDim.x + threadIdx.x;
    size_t stride = (size_t)gridDim.x * blockDim.x;
    const size_t n = (size_t)TOT * PDIM / 4;
    __nv_bfloat162* o = (__nv_bfloat162*)g_W1b;
    for (; i < n; i += stride) {
        float4 v = p[i];
        o[2 * i]     = __floats2bfloat162_rn(v.x, v.y);
        o[2 * i + 1] = __floats2bfloat162_rn(v.z, v.w);
    }
}
__global__ void cvt_w2_kernel(const float* __restrict__ p, const float* __restrict__ gamma) {
    size_t i = (size_t)blockIdx.x * blockDim.x + threadIdx.x;
    size_t stride = (size_t)gridDim.x * blockDim.x;
    const size_t n = (size_t)CS * TOT;
    for (; i < n; i += stride) {
        int c = (int)(i & (TOT - 1));
        g_W2b[i] = __float2bfloat16_rn(p[i] * gamma[c]);
    }
}

__global__ void gb_kernel(const float* __restrict__ W2, const float* __restrict__ gamma,
                          const float* __restrict__ beta, const float* __restrict__ b2) {
    int j = blockIdx.x;
    int tid = threadIdx.x, lane = tid & 31, wid = tid >> 5;
    __shared__ float sg[8], sb[8];
    float ag = 0.f, ab = 0.f;
    for (int c = tid; c < TOT; c += 256) {
        float w = W2[(size_t)j * TOT + c];
        ag += gamma[c] * w;
        ab += beta[c] * w;
    }
    #pragma unroll
    for (int off = 16; off; off >>= 1) {
        ag += __shfl_xor_sync(0xffffffffu, ag, off);
        ab += __shfl_xor_sync(0xffffffffu, ab, off);
    }
    if (lane == 0) { sg[wid] = ag; sb[wid] = ab; }
    __syncthreads();
    if (tid == 0) {
        float a = 0.f, b = 0.f;
        for (int w = 0; w < 8; w++) { a += sg[w]; b += sb[w]; }
        g_G[j] = a; g_Bt2[j] = b + b2[j];
    }
}

__global__ void transpose_lt_kernel(const float* __restrict__ ls) {
    __shared__ float t[32][33];
    int o0 = blockIdx.x * 32, v0 = blockIdx.y * 32;
    int tx = threadIdx.x, ty = threadIdx.y;
    #pragma unroll
    for (int k = 0; k < 32; k += 8)
        t[ty + k][tx] = ls[(size_t)(o0 + ty + k) * SELF_IN + (v0 + tx)];
    __syncthreads();
    #pragma unroll
    for (int k = 0; k < 32; k += 8)
        g_LTb[(size_t)(v0 + ty + k) * SELF_OUT + (o0 + tx)] = __float2bfloat16_rn(t[tx][ty + k]);
}

__global__ void count_kernel(const int* __restrict__ idx) {
    int i = blockIdx.x * blockDim.x + threadIdx.x;
    int v = (idx[i] >= 0) ? 1 : 0;
    #pragma unroll
    for (int off = 16; off; off >>= 1) v += __shfl_xor_sync(0xffffffffu, v, off);
    if ((threadIdx.x & 31) == 0) atomicAdd(&g_cnt, v);
}

__global__ void stats_kernel() {
    int r = blockIdx.x * blockDim.x + threadIdx.x;
    if (r < NROWS) {
        float mu  = g_s[r] * (1.f / TOT);
        float var = g_s2[r] * (1.f / TOT) - mu * mu;
        float inv = rsqrtf(var + LN_EPS);
        g_inv[r] = inv;
        g_muinv[r] = mu * inv;
    }
}

__global__ void finalize_kernel(float* out, int out_size) {
    out[0] = (float)g_acc;
    if (out_size > 1) out[1] = (float)g_cnt;
}

// ================= GEMM1: x = relu(pred@W1^T + b1 + self), stats =================
// BM=128 BN=128 BK=32, 3-stage cp.async, ldmatrix, 256 threads (8 warps 4m x 2n)
// smem: As 3x10240B @0, Bs 3x10240B @30720; overlay: LTs 256x136 bf16 @0, sidx @69632
#define G1_BS_OFF 30720
#define G1_LTS_STRIDE 136
#define G1_LTS_BYTES  (CS * G1_LTS_STRIDE * 2)   // 69632
#define G1_DSMEM      (G1_LTS_BYTES + 128 * 8 * 4)  // 73728

__global__ __launch_bounds__(256, 2) void gemm1_kernel(const int* __restrict__ idx,
                                                       const float* __restrict__ b1) {
    extern __shared__ __align__(128) char sm[];
    const uint32_t smb = smem_u32(sm);
    __nv_bfloat16* LTs = (__nv_bfloat16*)sm;
    int* sidx = (int*)(sm + G1_LTS_BYTES);

    const int tid = threadIdx.x, lane = tid & 31, wid = tid >> 5;
    const int wm = wid & 3, wn = wid >> 2;
    const int m0 = blockIdx.y * 128, n0 = blockIdx.x * 128;

    float acc[2][8][4];
    #pragma unroll
    for (int a = 0; a < 2; a++)
        #pragma unroll
        for (int b = 0; b < 8; b++)
            #pragma unroll
            for (int c = 0; c < 4; c++) acc[a][b][c] = 0.f;

    const __nv_bfloat16* Ag = g_predb + (size_t)m0 * PDIM;
    const __nv_bfloat16* Bg = g_W1b + (size_t)n0 * PDIM;

    auto load_stage = [&](int kt, int st) {
        const int k0 = kt * 32;
        #pragma unroll
        for (int i = 0; i < 2; i++) {
            int q = tid + i * 256, r = q >> 2, c = q & 3;
            cp_async16(sm + st * 10240 + r * 80 + c * 16, Ag + (size_t)r * PDIM + k0 + c * 8);
        }
        #pragma unroll
        for (int i = 0; i < 2; i++) {
            int q = tid + i * 256, r = q >> 2, c = q & 3;
            cp_async16(sm + G1_BS_OFF + st * 10240 + r * 80 + c * 16, Bg + (size_t)r * PDIM + k0 + c * 8);
        }
        cp_commit();
    };

    load_stage(0, 0); load_stage(1, 1);

    // ldmatrix lane offsets (bytes)
    const uint32_t offA = smb + ((wm * 32 + (lane & 15)) * 40 + (lane >> 4) * 8) * 2;
    const uint32_t offB = smb + G1_BS_OFF +
        ((wn * 64 + ((lane >> 4) << 3) + (lane & 7)) * 40 + ((lane >> 3) & 1) * 8) * 2;

    const int KT = PDIM / 32; // 16
    for (int kt = 0; kt < KT; kt++) {
        int st = kt % 3;
        if (kt == KT - 1) asm volatile("cp.async.wait_group 0;\n" ::: "memory");
        else              asm volatile("cp.async.wait_group 1;\n" ::: "memory");
        __syncthreads();
        if (kt + 2 < KT) load_stage(kt + 2, (kt + 2) % 3);
        uint32_t aB = offA + st * 10240;
        uint32_t bB = offB + st * 10240;
        #pragma unroll
        for (int ks = 0; ks < 2; ks++) {
            uint32_t a[2][4], b[4][4];
            ldsm_x4(a[0], aB + ks * 32);
            ldsm_x4(a[1], aB + ks * 32 + 1280);
            #pragma unroll
            for (int np = 0; np < 4; np++)
                ldsm_x4(b[np], bB + ks * 32 + np * 1280);
            #pragma unroll
            for (int mi = 0; mi < 2; mi++)
                #pragma unroll
                for (int ni = 0; ni < 8; ni++)
                    mma16816(acc[mi][ni], a[mi], &b[ni >> 1][(ni & 1) * 2]);
        }
    }
    __syncthreads();

    // -------- fused epilogue: + b1 + self, relu, stats, store bf16 x --------
    const bool has_self = (n0 >= CS);

    if (tid < 128) {
        int vals[8];
        #pragma unroll
        for (int j = 0; j < 8; j++) vals[j] = idx[(size_t)(m0 + tid) * NC + j];
        #pragma unroll
        for (int j = 0; j < 8; j++) {
            int v = vals[j];
            bool dup = false;
            for (int j2 = 0; j2 < j; j2++)
                if (vals[j2] == v) dup = true;
            sidx[tid * 8 + j] = (v >= 0 && v < CS && !dup) ? v : -1;
        }
    }
    if (has_self) {
        int o0 = n0 - CS;
        #pragma unroll
        for (int it = 0; it < 16; it++) {
            int ch = tid + it * 256;
            int v = ch >> 4, c8 = (ch & 15) * 8;
            *(uint4*)&LTs[v * G1_LTS_STRIDE + c8] =
                *(const uint4*)&g_LTb[(size_t)v * SELF_OUT + o0 + c8];
        }
    }
    __syncthreads();

    const int lr = lane >> 2, lc = (lane & 3) * 2;
    #pragma unroll
    for (int mi = 0; mi < 2; mi++) {
        #pragma unroll
        for (int h = 0; h < 2; h++) {
            int rloc = wm * 32 + lr + mi * 16 + h * 8;
            int rglob = m0 + rloc;
            int vs[8];
            #pragma unroll
            for (int j = 0; j < 8; j++) vs[j] = sidx[rloc * 8 + j];
            float s = 0.f, s2 = 0.f;
            #pragma unroll
            for (int ni = 0; ni < 8; ni++) {
                int cl = wn * 64 + ni * 8 + lc;
                int cg = n0 + cl;
                float x0 = acc[mi][ni][h * 2]     + __ldg(&b1[cg]);
                float x1 = acc[mi][ni][h * 2 + 1] + __ldg(&b1[cg + 1]);
                if (has_self) {
                    #pragma unroll
                    for (int j = 0; j < 8; j++) {
                        int v = vs[j];
                        if (v >= 0) {
                            __nv_bfloat162 p = *(const __nv_bfloat162*)&LTs[v * G1_LTS_STRIDE + cl];
                            x0 += __bfloat162float(p.x);
                            x1 += __bfloat162float(p.y);
                        }
                    }
                }
                x0 = fmaxf(x0, 0.f); x1 = fmaxf(x1, 0.f);
                s += x0 + x1; s2 += x0 * x0 + x1 * x1;
                *(__nv_bfloat162*)&g_hidden[(size_t)rglob * TOT + cg] = __floats2bfloat162_rn(x0, x1);
            }
            s  += __shfl_xor_sync(0xffffffffu, s, 1);
            s  += __shfl_xor_sync(0xffffffffu, s, 2);
            s2 += __shfl_xor_sync(0xffffffffu, s2, 1);
            s2 += __shfl_xor_sync(0xffffffffu, s2, 2);
            if ((lane & 3) == 0) {
                atomicAdd(&g_s[rglob], s);
                atomicAdd(&g_s2[rglob], s2);
            }
        }
    }
}

// ================= GEMM2 + LN fold + log-softmax + gather-reduce =================
// BM=64 BN=256 BK=32, 3-stage, ldmatrix, 256 threads (8 warps 2m x 4n)
// smem: As 3x5120B @0, Bs 3x20480B @15360; overlay: Ls 64x260 f32 @0; red @76800
#define G2_BS_OFF 15360
#define G2_RED_OFF 76800
#define G2_DSMEM   76832

__global__ __launch_bounds__(256, 2) void gemm2_kernel(const int* __restrict__ idx) {
    extern __shared__ __align__(128) char sm[];
    const uint32_t smb = smem_u32(sm);
    float* Ls = (float*)sm;
    float* sred = (float*)(sm + G2_RED_OFF);

    const int tid = threadIdx.x, lane = tid & 31, wid = tid >> 5;
    const int wm = wid & 1, wn = wid >> 1;
    const int m0 = blockIdx.x * 64;

    float acc[2][8][4];
    #pragma unroll
    for (int a = 0; a < 2; a++)
        #pragma unroll
        for (int b = 0; b < 8; b++)
            #pragma unroll
            for (int c = 0; c < 4; c++) acc[a][b][c] = 0.f;

    const __nv_bfloat16* Ag = g_hidden + (size_t)m0 * TOT;
    const __nv_bfloat16* Bg = g_W2b;

    auto load_stage = [&](int kt, int st) {
        const int k0 = kt * 32;
        {
            int r = tid >> 2, c = tid & 3;
            cp_async16(sm + st * 5120 + r * 80 + c * 16, Ag + (size_t)r * TOT + k0 + c * 8);
        }
        #pragma unroll
        for (int i = 0; i < 4; i++) {
            int q = tid + i * 256, r = q >> 2, c = q & 3;
            cp_async16(sm + G2_BS_OFF + st * 20480 + r * 80 + c * 16, Bg + (size_t)r * TOT + k0 + c * 8);
        }
        cp_commit();
    };

    load_stage(0, 0); load_stage(1, 1);

    const uint32_t offA = smb + ((wm * 32 + (lane & 15)) * 40 + (lane >> 4) * 8) * 2;
    const uint32_t offB = smb + G2_BS_OFF +
        ((wn * 64 + ((lane >> 4) << 3) + (lane & 7)) * 40 + ((lane >> 3) & 1) * 8) * 2;

    const int KT = TOT / 32;  // 64
    for (int kt = 0; kt < KT; kt++) {
        int st = kt % 3;
        if (kt == KT - 1) asm volatile("cp.async.wait_group 0;\n" ::: "memory");
        else              asm volatile("cp.async.wait_group 1;\n" ::: "memory");
        __syncthreads();
        if (kt + 2 < KT) load_stage(kt + 2, (kt + 2) % 3);
        uint32_t aB = offA + st * 5120;
        uint32_t bB = offB + st * 20480;
        #pragma unroll
        for (int ks = 0; ks < 2; ks++) {
            uint32_t a[2][4], b[4][4];
            ldsm_x4(a[0], aB + ks * 32);
            ldsm_x4(a[1], aB + ks * 32 + 1280);
            #pragma unroll
            for (int np = 0; np < 4; np++)
                ldsm_x4(b[np], bB + ks * 32 + np * 1280);
            #pragma unroll
            for (int mi = 0; mi < 2; mi++)
                #pragma unroll
                for (int ni = 0; ni < 8; ni++)
                    mma16816(acc[mi][ni], a[mi], &b[ni >> 1][(ni & 1) * 2]);
        }
    }
    __syncthreads();

    // stage logits into smem with LN affine folded: logit = acc*inv - muinv*G[c] + Bt2[c]
    {
        int r0 = wm * 32 + (lane >> 2);
        int c0 = wn * 64 + (lane & 3) * 2;
        #pragma unroll
        for (int mi = 0; mi < 2; mi++) {
            #pragma unroll
            for (int h = 0; h < 2; h++) {
                int r = r0 + mi * 16 + h * 8;
                float inv = __ldg(&g_inv[m0 + r]);
                float mui = __ldg(&g_muinv[m0 + r]);
                #pragma unroll
                for (int ni = 0; ni < 8; ni++) {
                    int c = c0 + ni * 8;
                    float g0 = __ldg(&g_G[c]),   g1 = __ldg(&g_G[c + 1]);
                    float t0 = __ldg(&g_Bt2[c]), t1 = __ldg(&g_Bt2[c + 1]);
                    Ls[r * 260 + c]     = acc[mi][ni][h * 2]     * inv - mui * g0 + t0;
                    Ls[r * 260 + c + 1] = acc[mi][ni][h * 2 + 1] * inv - mui * g1 + t1;
                }
            }
        }
    }
    __syncthreads();

    // per-row logsumexp + gather (4 threads/row, interleaved columns -> conflict-free)
    int row = tid >> 2, sub = tid & 3;
    const float* Lr = Ls + row * 260;
    float m = -1e30f;
    #pragma unroll
    for (int i = 0; i < 64; i++) m = fmaxf(m, Lr[sub + i * 4]);
    m = fmaxf(m, __shfl_xor_sync(0xffffffffu, m, 1));
    m = fmaxf(m, __shfl_xor_sync(0xffffffffu, m, 2));
    float se = 0.f;
    #pragma unroll
    for (int i = 0; i < 64; i++) se += __expf(Lr[sub + i * 4] - m);
    se += __shfl_xor_sync(0xffffffffu, se, 1);
    se += __shfl_xor_sync(0xffffffffu, se, 2);
    float lse = m + logf(se);

    float contrib = 0.f;
    if (sub == 0) {
        int gn = m0 + row;
        int vals[8];
        #pragma unroll
        for (int j = 0; j < 8; j++) vals[j] = idx[(size_t)gn * NC + j];
        float a = 0.f; int cnt = 0;
        #pragma unroll
        for (int j = 0; j < 8; j++) {
            int vv = vals[j];
            if (vv < 0 || vv >= CS) continue;
            bool dup = false;
            for (int j2 = 0; j2 < j; j2++)
                if (vals[j2] == vv) dup = true;
            if (dup) continue;
            a += Lr[vv]; cnt++;
        }
        contrib = a - (float)cnt * lse;
    }
    #pragma unroll
    for (int off = 16; off; off >>= 1) contrib += __shfl_xor_sync(0xffffffffu, contrib, off);
    if (lane == 0) sred[wid] = contrib;
    __syncthreads();
    if (tid == 0) {
        float t = 0.f;
        for (int w = 0; w < 8; w++) t += sred[w];
        atomicAdd(&g_acc, (double)t);
    }
}

// ---------------- launcher ----------------
extern "C" void kernel_launch(void* const* d_in, const int* in_sizes, int n_in,
                              void* d_out, int out_size) {
    const float* pred  = (const float*)d_in[0];
    const int*   idx   = (const int*)  d_in[1];
    const float* W1    = (const float*)d_in[2];
    const float* b1    = (const float*)d_in[3];
    const float* ls    = (const float*)d_in[4];
    const float* gamma = (const float*)d_in[5];
    const float* beta  = (const float*)d_in[6];
    const float* W2    = (const float*)d_in[7];
    const float* b2    = (const float*)d_in[8];
    float* out = (float*)d_out;

    cudaFuncSetAttribute(gemm1_kernel, cudaFuncAttributeMaxDynamicSharedMemorySize, G1_DSMEM);
    cudaFuncSetAttribute(gemm2_kernel, cudaFuncAttributeMaxDynamicSharedMemorySize, G2_DSMEM);

    zero_kernel<<<1, 1>>>();
    clear_stats_kernel<<<NROWS / 256, 256>>>();
    cvt_pred_kernel<<<2048, 256>>>((const float4*)pred);
    cvt_w1_kernel<<<512, 256>>>((const float4*)W1);
    cvt_w2_kernel<<<512, 256>>>(W2, gamma);
    transpose_lt_kernel<<<dim3(SELF_OUT / 32, CS / 32), dim3(32, 8)>>>(ls);
    gb_kernel<<<CS, 256>>>(W2, gamma, beta, b2);
    count_kernel<<<(NROWS * NC) / 256, 256>>>(idx);

    gemm1_kernel<<<dim3(TOT / 128, NROWS / 128), 256, G1_DSMEM>>>(idx, b1);
    stats_kernel<<<NROWS / 256, 256>>>();
    gemm2_kernel<<<NROWS / 64, 256, G2_DSMEM>>>(idx);

    finalize_kernel<<<1, 1>>>(out, out_size);
}

// round 10
// speedup vs baseline: 2.0765x; 1.0031x over previous
#include <cuda_runtime.h>
#include <cuda_bf16.h>
#include <cstdint>

// Problem constants
#define NROWS 32768        // B*T
#define PDIM  512
#define NC    8
#define CS    256
#define TOT   2048         // NC*CS
#define SELF_OUT 1792
#define SELF_IN  1792
#define LN_EPS 1e-5f

// ---------------- device scratch (allocation-free rule) ----------------
__device__ __nv_bfloat16 g_predb[(size_t)NROWS * PDIM];        // 32 MB
__device__ __nv_bfloat16 g_W1b[(size_t)TOT * PDIM];            // 2 MB
__device__ __nv_bfloat16 g_W2b[(size_t)CS * TOT];              // 1 MB  W2g = W2[0:256]*gamma
__device__ __nv_bfloat16 g_LTb[(size_t)CS * SELF_OUT];         // LT[v][o] = linear_self[o][v]
__device__ __nv_bfloat16 g_hidden[(size_t)NROWS * TOT];        // 128 MB (post-relu x)
__device__ float g_s[NROWS], g_s2[NROWS];
__device__ float g_inv[NROWS], g_muinv[NROWS];
__device__ float g_G[CS], g_Bt2[CS];
__device__ double g_acc;
__device__ int    g_cnt;

// ---------------- helpers ----------------
__device__ __forceinline__ uint32_t smem_u32(const void* p) {
    uint32_t a;
    asm("{ .reg .u64 t; cvta.to.shared.u64 t, %1; cvt.u32.u64 %0, t; }" : "=r"(a) : "l"(p));
    return a;
}
__device__ __forceinline__ void cp_async16(void* sdst, const void* gsrc) {
    uint32_t s = (uint32_t)__cvta_generic_to_shared(sdst);
    asm volatile("cp.async.cg.shared.global [%0], [%1], 16;\n" :: "r"(s), "l"(gsrc));
}
__device__ __forceinline__ void cp_commit() { asm volatile("cp.async.commit_group;\n"); }

__device__ __forceinline__ void ldsm_x4(uint32_t* r, uint32_t addr) {
    asm volatile("ldmatrix.sync.aligned.m8n8.x4.shared.b16 {%0,%1,%2,%3}, [%4];"
        : "=r"(r[0]), "=r"(r[1]), "=r"(r[2]), "=r"(r[3]) : "r"(addr));
}

__device__ __forceinline__ void mma16816(float* c, const uint32_t* a, const uint32_t* b) {
    asm volatile(
        "mma.sync.aligned.m16n8k16.row.col.f32.bf16.bf16.f32 "
        "{%0,%1,%2,%3}, {%4,%5,%6,%7}, {%8,%9}, {%0,%1,%2,%3};\n"
        : "+f"(c[0]), "+f"(c[1]), "+f"(c[2]), "+f"(c[3])
        : "r"(a[0]), "r"(a[1]), "r"(a[2]), "r"(a[3]), "r"(b[0]), "r"(b[1]));
}

__device__ __forceinline__ uint32_t pack_bf2(float a, float b) {
    __nv_bfloat162 h = __floats2bfloat162_rn(a, b);
    return *reinterpret_cast<uint32_t*>(&h);
}

// ---------------- small prep kernels ----------------
__global__ void zeros_kernel() {
    int i = blockIdx.x * blockDim.x + threadIdx.x;
    if (i < NROWS) { g_s[i] = 0.f; g_s2[i] = 0.f; }
    if (i == 0) { g_acc = 0.0; g_cnt = 0; }
}

// 8 floats per thread, 16B store
__global__ void cvt_pred_kernel(const float4* __restrict__ p) {
    size_t i = (size_t)blockIdx.x * blockDim.x + threadIdx.x;   // grid sized exactly
    float4 v0 = p[2 * i], v1 = p[2 * i + 1];
    uint4 o;
    o.x = pack_bf2(v0.x, v0.y); o.y = pack_bf2(v0.z, v0.w);
    o.z = pack_bf2(v1.x, v1.y); o.w = pack_bf2(v1.z, v1.w);
    ((uint4*)g_predb)[i] = o;
}
__global__ void cvt_w1_kernel(const float4* __restrict__ p) {
    size_t i = (size_t)blockIdx.x * blockDim.x + threadIdx.x;
    float4 v0 = p[2 * i], v1 = p[2 * i + 1];
    uint4 o;
    o.x = pack_bf2(v0.x, v0.y); o.y = pack_bf2(v0.z, v0.w);
    o.z = pack_bf2(v1.x, v1.y); o.w = pack_bf2(v1.z, v1.w);
    ((uint4*)g_W1b)[i] = o;
}
// W2g = W2[0:256] * gamma (broadcast over columns)
__global__ void cvt_w2_kernel(const float4* __restrict__ p, const float* __restrict__ gamma) {
    size_t i = (size_t)blockIdx.x * blockDim.x + threadIdx.x;
    int c0 = (int)((8 * i) & (TOT - 1));
    float4 v0 = p[2 * i], v1 = p[2 * i + 1];
    uint4 o;
    o.x = pack_bf2(v0.x * __ldg(&gamma[c0]),     v0.y * __ldg(&gamma[c0 + 1]));
    o.y = pack_bf2(v0.z * __ldg(&gamma[c0 + 2]), v0.w * __ldg(&gamma[c0 + 3]));
    o.z = pack_bf2(v1.x * __ldg(&gamma[c0 + 4]), v1.y * __ldg(&gamma[c0 + 5]));
    o.w = pack_bf2(v1.z * __ldg(&gamma[c0 + 6]), v1.w * __ldg(&gamma[c0 + 7]));
    ((uint4*)g_W2b)[i] = o;
}

__global__ void gb_kernel(const float* __restrict__ W2, const float* __restrict__ gamma,
                          const float* __restrict__ beta, const float* __restrict__ b2) {
    int j = blockIdx.x;
    int tid = threadIdx.x, lane = tid & 31, wid = tid >> 5;
    __shared__ float sg[8], sb[8];
    float ag = 0.f, ab = 0.f;
    for (int c = tid; c < TOT; c += 256) {
        float w = W2[(size_t)j * TOT + c];
        ag += gamma[c] * w;
        ab += beta[c] * w;
    }
    #pragma unroll
    for (int off = 16; off; off >>= 1) {
        ag += __shfl_xor_sync(0xffffffffu, ag, off);
        ab += __shfl_xor_sync(0xffffffffu, ab, off);
    }
    if (lane == 0) { sg[wid] = ag; sb[wid] = ab; }
    __syncthreads();
    if (tid == 0) {
        float a = 0.f, b = 0.f;
        for (int w = 0; w < 8; w++) { a += sg[w]; b += sb[w]; }
        g_G[j] = a; g_Bt2[j] = b + b2[j];
    }
}

__global__ void transpose_lt_kernel(const float* __restrict__ ls) {
    __shared__ float t[32][33];
    int o0 = blockIdx.x * 32, v0 = blockIdx.y * 32;
    int tx = threadIdx.x, ty = threadIdx.y;
    #pragma unroll
    for (int k = 0; k < 32; k += 8)
        t[ty + k][tx] = ls[(size_t)(o0 + ty + k) * SELF_IN + (v0 + tx)];
    __syncthreads();
    #pragma unroll
    for (int k = 0; k < 32; k += 8)
        g_LTb[(size_t)(v0 + ty + k) * SELF_OUT + (o0 + tx)] = __float2bfloat16_rn(t[tx][ty + k]);
}

__global__ void count_kernel(const int* __restrict__ idx) {
    int i = blockIdx.x * blockDim.x + threadIdx.x;
    int v = (idx[i] >= 0) ? 1 : 0;
    #pragma unroll
    for (int off = 16; off; off >>= 1) v += __shfl_xor_sync(0xffffffffu, v, off);
    if ((threadIdx.x & 31) == 0) atomicAdd(&g_cnt, v);
}

__global__ void stats_kernel() {
    int r = blockIdx.x * blockDim.x + threadIdx.x;
    if (r < NROWS) {
        float mu  = g_s[r] * (1.f / TOT);
        float var = g_s2[r] * (1.f / TOT) - mu * mu;
        float inv = rsqrtf(var + LN_EPS);
        g_inv[r] = inv;
        g_muinv[r] = mu * inv;
    }
}

__global__ void finalize_kernel(float* out, int out_size) {
    out[0] = (float)g_acc;
    if (out_size > 1) out[1] = (float)g_cnt;
}

// ================= GEMM1: x = relu(pred@W1^T + b1 + self), stats =================
// BM=128 BN=128 BK=64, 3-stage cp.async, ldmatrix, 256 threads (8 warps 4m x 2n)
// Stage pitch: 144B/row (64 cols + 8 pad). A stage 18432B, B stage 18432B.
// smem: As 3x18432 @0, Bs 3x18432 @55296 (end 110592)
// overlay (post-mainloop): LTs 256x136 bf16 @0 (69632B), sidx 4096B @69632
#define G1_ST_BYTES 18432
#define G1_BS_OFF   55296
#define G1_LTS_STRIDE 136
#define G1_SIDX_OFF 69632
#define G1_DSMEM    110592

__global__ __launch_bounds__(256, 2) void gemm1_kernel(const int* __restrict__ idx,
                                                       const float* __restrict__ b1) {
    extern __shared__ __align__(128) char sm[];
    const uint32_t smb = smem_u32(sm);
    __nv_bfloat16* LTs = (__nv_bfloat16*)sm;
    int* sidx = (int*)(sm + G1_SIDX_OFF);

    const int tid = threadIdx.x, lane = tid & 31, wid = tid >> 5;
    const int wm = wid & 3, wn = wid >> 2;
    const int m0 = blockIdx.y * 128, n0 = blockIdx.x * 128;

    float acc[2][8][4];
    #pragma unroll
    for (int a = 0; a < 2; a++)
        #pragma unroll
        for (int b = 0; b < 8; b++)
            #pragma unroll
            for (int c = 0; c < 4; c++) acc[a][b][c] = 0.f;

    const __nv_bfloat16* Ag = g_predb + (size_t)m0 * PDIM;
    const __nv_bfloat16* Bg = g_W1b + (size_t)n0 * PDIM;

    // per stage: A 128 rows x 8 chunks(16B) = 1024 chunks -> 4/thread; B same
    auto load_stage = [&](int kt, int st) {
        const int k0 = kt * 64;
        #pragma unroll
        for (int i = 0; i < 4; i++) {
            int q = tid + i * 256, r = q >> 3, c = q & 7;
            cp_async16(sm + st * G1_ST_BYTES + r * 144 + c * 16, Ag + (size_t)r * PDIM + k0 + c * 8);
        }
        #pragma unroll
        for (int i = 0; i < 4; i++) {
            int q = tid + i * 256, r = q >> 3, c = q & 7;
            cp_async16(sm + G1_BS_OFF + st * G1_ST_BYTES + r * 144 + c * 16, Bg + (size_t)r * PDIM + k0 + c * 8);
        }
        cp_commit();
    };

    load_stage(0, 0); load_stage(1, 1);

    // ldmatrix lane offsets (bytes), row pitch 72 elements (144B)
    const uint32_t offA = smb + ((wm * 32 + (lane & 15)) * 72 + (lane >> 4) * 8) * 2;
    const uint32_t offB = smb + G1_BS_OFF +
        ((wn * 64 + ((lane >> 4) << 3) + (lane & 7)) * 72 + ((lane >> 3) & 1) * 8) * 2;

    const int KT = PDIM / 64; // 8
    for (int kt = 0; kt < KT; kt++) {
        int st = kt % 3;
        if (kt == KT - 1) asm volatile("cp.async.wait_group 0;\n" ::: "memory");
        else              asm volatile("cp.async.wait_group 1;\n" ::: "memory");
        __syncthreads();
        if (kt + 2 < KT) load_stage(kt + 2, (kt + 2) % 3);
        uint32_t aB = offA + st * G1_ST_BYTES;
        uint32_t bB = offB + st * G1_ST_BYTES;
        #pragma unroll
        for (int ks = 0; ks < 4; ks++) {
            uint32_t a[2][4], b[4][4];
            ldsm_x4(a[0], aB + ks * 32);
            ldsm_x4(a[1], aB + ks * 32 + 2304);      // +16 rows * 144B
            #pragma unroll
            for (int np = 0; np < 4; np++)
                ldsm_x4(b[np], bB + ks * 32 + np * 2304);
            #pragma unroll
            for (int mi = 0; mi < 2; mi++)
                #pragma unroll
                for (int ni = 0; ni < 8; ni++)
                    mma16816(acc[mi][ni], a[mi], &b[ni >> 1][(ni & 1) * 2]);
        }
        __syncthreads();
    }

    // -------- fused epilogue: + b1 + self, relu, stats, store bf16 x --------
    const bool has_self = (n0 >= CS);

    if (tid < 128) {
        int vals[8];
        #pragma unroll
        for (int j = 0; j < 8; j++) vals[j] = idx[(size_t)(m0 + tid) * NC + j];
        #pragma unroll
        for (int j = 0; j < 8; j++) {
            int v = vals[j];
            bool dup = false;
            for (int j2 = 0; j2 < j; j2++)
                if (vals[j2] == v) dup = true;
            sidx[tid * 8 + j] = (v >= 0 && v < CS && !dup) ? v : -1;
        }
    }
    if (has_self) {
        int o0 = n0 - CS;
        #pragma unroll
        for (int it = 0; it < 16; it++) {
            int ch = tid + it * 256;
            int v = ch >> 4, c8 = (ch & 15) * 8;
            *(uint4*)&LTs[v * G1_LTS_STRIDE + c8] =
                *(const uint4*)&g_LTb[(size_t)v * SELF_OUT + o0 + c8];
        }
    }
    __syncthreads();

    const int lr = lane >> 2, lc = (lane & 3) * 2;
    #pragma unroll
    for (int mi = 0; mi < 2; mi++) {
        #pragma unroll
        for (int h = 0; h < 2; h++) {
            int rloc = wm * 32 + lr + mi * 16 + h * 8;
            int rglob = m0 + rloc;
            int vs[8];
            #pragma unroll
            for (int j = 0; j < 8; j++) vs[j] = sidx[rloc * 8 + j];
            float s = 0.f, s2 = 0.f;
            #pragma unroll
            for (int ni = 0; ni < 8; ni++) {
                int cl = wn * 64 + ni * 8 + lc;
                int cg = n0 + cl;
                float x0 = acc[mi][ni][h * 2]     + __ldg(&b1[cg]);
                float x1 = acc[mi][ni][h * 2 + 1] + __ldg(&b1[cg + 1]);
                if (has_self) {
                    #pragma unroll
                    for (int j = 0; j < 8; j++) {
                        int v = vs[j];
                        if (v >= 0) {
                            __nv_bfloat162 p = *(const __nv_bfloat162*)&LTs[v * G1_LTS_STRIDE + cl];
                            x0 += __bfloat162float(p.x);
                            x1 += __bfloat162float(p.y);
                        }
                    }
                }
                x0 = fmaxf(x0, 0.f); x1 = fmaxf(x1, 0.f);
                s += x0 + x1; s2 += x0 * x0 + x1 * x1;
                *(__nv_bfloat162*)&g_hidden[(size_t)rglob * TOT + cg] = __floats2bfloat162_rn(x0, x1);
            }
            s  += __shfl_xor_sync(0xffffffffu, s, 1);
            s  += __shfl_xor_sync(0xffffffffu, s, 2);
            s2 += __shfl_xor_sync(0xffffffffu, s2, 1);
            s2 += __shfl_xor_sync(0xffffffffu, s2, 2);
            if ((lane & 3) == 0) {
                atomicAdd(&g_s[rglob], s);
                atomicAdd(&g_s2[rglob], s2);
            }
        }
    }
}

// ================= GEMM2 + LN fold + log-softmax + gather-reduce =================
// BM=64 BN=256 BK=32, 3-stage, ldmatrix, 256 threads (8 warps 2m x 4n)
// smem: As 3x5120B @0, Bs 3x20480B @15360; overlay: Ls 64x260 f32 @0; red @76800
#define G2_BS_OFF 15360
#define G2_RED_OFF 76800
#define G2_DSMEM   76832

__global__ __launch_bounds__(256, 2) void gemm2_kernel(const int* __restrict__ idx) {
    extern __shared__ __align__(128) char sm[];
    const uint32_t smb = smem_u32(sm);
    float* Ls = (float*)sm;
    float* sred = (float*)(sm + G2_RED_OFF);

    const int tid = threadIdx.x, lane = tid & 31, wid = tid >> 5;
    const int wm = wid & 1, wn = wid >> 1;
    const int m0 = blockIdx.x * 64;

    float acc[2][8][4];
    #pragma unroll
    for (int a = 0; a < 2; a++)
        #pragma unroll
        for (int b = 0; b < 8; b++)
            #pragma unroll
            for (int c = 0; c < 4; c++) acc[a][b][c] = 0.f;

    const __nv_bfloat16* Ag = g_hidden + (size_t)m0 * TOT;
    const __nv_bfloat16* Bg = g_W2b;

    auto load_stage = [&](int kt, int st) {
        const int k0 = kt * 32;
        {
            int r = tid >> 2, c = tid & 3;
            cp_async16(sm + st * 5120 + r * 80 + c * 16, Ag + (size_t)r * TOT + k0 + c * 8);
        }
        #pragma unroll
        for (int i = 0; i < 4; i++) {
            int q = tid + i * 256, r = q >> 2, c = q & 3;
            cp_async16(sm + G2_BS_OFF + st * 20480 + r * 80 + c * 16, Bg + (size_t)r * TOT + k0 + c * 8);
        }
        cp_commit();
    };

    load_stage(0, 0); load_stage(1, 1);

    const uint32_t offA = smb + ((wm * 32 + (lane & 15)) * 40 + (lane >> 4) * 8) * 2;
    const uint32_t offB = smb + G2_BS_OFF +
        ((wn * 64 + ((lane >> 4) << 3) + (lane & 7)) * 40 + ((lane >> 3) & 1) * 8) * 2;

    const int KT = TOT / 32;  // 64
    for (int kt = 0; kt < KT; kt++) {
        int st = kt % 3;
        if (kt == KT - 1) asm volatile("cp.async.wait_group 0;\n" ::: "memory");
        else              asm volatile("cp.async.wait_group 1;\n" ::: "memory");
        __syncthreads();
        if (kt + 2 < KT) load_stage(kt + 2, (kt + 2) % 3);
        uint32_t aB = offA + st * 5120;
        uint32_t bB = offB + st * 20480;
        #pragma unroll
        for (int ks = 0; ks < 2; ks++) {
            uint32_t a[2][4], b[4][4];
            ldsm_x4(a[0], aB + ks * 32);
            ldsm_x4(a[1], aB + ks * 32 + 1280);
            #pragma unroll
            for (int np = 0; np < 4; np++)
                ldsm_x4(b[np], bB + ks * 32 + np * 1280);
            #pragma unroll
            for (int mi = 0; mi < 2; mi++)
                #pragma unroll
                for (int ni = 0; ni < 8; ni++)
                    mma16816(acc[mi][ni], a[mi], &b[ni >> 1][(ni & 1) * 2]);
        }
    }
    __syncthreads();

    // stage logits into smem with LN affine folded: logit = acc*inv - muinv*G[c] + Bt2[c]
    {
        int r0 = wm * 32 + (lane >> 2);
        int c0 = wn * 64 + (lane & 3) * 2;
        #pragma unroll
        for (int mi = 0; mi < 2; mi++) {
            #pragma unroll
            for (int h = 0; h < 2; h++) {
                int r = r0 + mi * 16 + h * 8;
                float inv = __ldg(&g_inv[m0 + r]);
                float mui = __ldg(&g_muinv[m0 + r]);
                #pragma unroll
                for (int ni = 0; ni < 8; ni++) {
                    int c = c0 + ni * 8;
                    float g0 = __ldg(&g_G[c]),   g1 = __ldg(&g_G[c + 1]);
                    float t0 = __ldg(&g_Bt2[c]), t1 = __ldg(&g_Bt2[c + 1]);
                    Ls[r * 260 + c]     = acc[mi][ni][h * 2]     * inv - mui * g0 + t0;
                    Ls[r * 260 + c + 1] = acc[mi][ni][h * 2 + 1] * inv - mui * g1 + t1;
                }
            }
        }
    }
    __syncthreads();

    // per-row logsumexp + gather (4 threads/row, interleaved columns -> conflict-free)
    int row = tid >> 2, sub = tid & 3;
    const float* Lr = Ls + row * 260;
    float m = -1e30f;
    #pragma unroll
    for (int i = 0; i < 64; i++) m = fmaxf(m, Lr[sub + i * 4]);
    m = fmaxf(m, __shfl_xor_sync(0xffffffffu, m, 1));
    m = fmaxf(m, __shfl_xor_sync(0xffffffffu, m, 2));
    float se = 0.f;
    #pragma unroll
    for (int i = 0; i < 64; i++) se += __expf(Lr[sub + i * 4] - m);
    se += __shfl_xor_sync(0xffffffffu, se, 1);
    se += __shfl_xor_sync(0xffffffffu, se, 2);
    float lse = m + logf(se);

    float contrib = 0.f;
    if (sub == 0) {
        int gn = m0 + row;
        int vals[8];
        #pragma unroll
        for (int j = 0; j < 8; j++) vals[j] = idx[(size_t)gn * NC + j];
        float a = 0.f; int cnt = 0;
        #pragma unroll
        for (int j = 0; j < 8; j++) {
            int vv = vals[j];
            if (vv < 0 || vv >= CS) continue;
            bool dup = false;
            for (int j2 = 0; j2 < j; j2++)
                if (vals[j2] == vv) dup = true;
            if (dup) continue;
            a += Lr[vv]; cnt++;
        }
        contrib = a - (float)cnt * lse;
    }
    #pragma unroll
    for (int off = 16; off; off >>= 1) contrib += __shfl_xor_sync(0xffffffffu, contrib, off);
    if (lane == 0) sred[wid] = contrib;
    __syncthreads();
    if (tid == 0) {
        float t = 0.f;
        for (int w = 0; w < 8; w++) t += sred[w];
        atomicAdd(&g_acc, (double)t);
    }
}

// ---------------- launcher ----------------
// Launch order puts gemm1 at index 5 so ncu (-s 5 -c 1) profiles it.
extern "C" void kernel_launch(void* const* d_in, const int* in_sizes, int n_in,
                              void* d_out, int out_size) {
    const float* pred  = (const float*)d_in[0];
    const int*   idx   = (const int*)  d_in[1];
    const float* W1    = (const float*)d_in[2];
    const float* b1    = (const float*)d_in[3];
    const float* ls    = (const float*)d_in[4];
    const float* gamma = (const float*)d_in[5];
    const float* beta  = (const float*)d_in[6];
    const float* W2    = (const float*)d_in[7];
    const float* b2    = (const float*)d_in[8];
    float* out = (float*)d_out;

    cudaFuncSetAttribute(gemm1_kernel, cudaFuncAttributeMaxDynamicSharedMemorySize, G1_DSMEM);
    cudaFuncSetAttribute(gemm2_kernel, cudaFuncAttributeMaxDynamicSharedMemorySize, G2_DSMEM);

    // 0..4: prep needed by gemm1
    cvt_pred_kernel<<<(NROWS * PDIM / 8) / 256, 256>>>((const float4*)pred);         // 0
    cvt_w1_kernel<<<(TOT * PDIM / 8) / 256, 256>>>((const float4*)W1);               // 1
    transpose_lt_kernel<<<dim3(SELF_OUT / 32, CS / 32), dim3(32, 8)>>>(ls);          // 2
    zeros_kernel<<<NROWS / 256, 256>>>();                                            // 3
    count_kernel<<<(NROWS * NC) / 256, 256>>>(idx);                                  // 4

    gemm1_kernel<<<dim3(TOT / 128, NROWS / 128), 256, G1_DSMEM>>>(idx, b1);          // 5 <- ncu

    // prep needed only by gemm2
    cvt_w2_kernel<<<(CS * TOT / 8) / 256, 256>>>((const float4*)W2, gamma);          // 6
    gb_kernel<<<CS, 256>>>(W2, gamma, beta, b2);                                     // 7
    stats_kernel<<<NROWS / 256, 256>>>();                                            // 8

    gemm2_kernel<<<NROWS / 64, 256, G2_DSMEM>>>(idx);                                // 9

    finalize_kernel<<<1, 1>>>(out, out_size);                                        // 10
}

// round 11
// speedup vs baseline: 2.0982x; 1.0104x over previous
#include <cuda_runtime.h>
#include <cuda_bf16.h>
#include <cstdint>

// Problem constants
#define NROWS 32768        // B*T
#define PDIM  512
#define NC    8
#define CS    256
#define TOT   2048         // NC*CS
#define SELF_OUT 1792
#define SELF_IN  1792
#define LN_EPS 1e-5f

// ---------------- device scratch (allocation-free rule) ----------------
__device__ __nv_bfloat16 g_predb[(size_t)NROWS * PDIM];        // 32 MB
__device__ __nv_bfloat16 g_W1b[(size_t)TOT * PDIM];            // 2 MB
__device__ __nv_bfloat16 g_W2b[(size_t)CS * TOT];              // 1 MB  W2g = W2[0:256]*gamma
__device__ __nv_bfloat16 g_LTb[(size_t)CS * SELF_OUT];         // LT[v][o] = linear_self[o][v]
__device__ __nv_bfloat16 g_hidden[(size_t)NROWS * TOT];        // 128 MB (post-relu x)
__device__ float g_s[NROWS], g_s2[NROWS];
__device__ float g_inv[NROWS], g_muinv[NROWS];
__device__ float g_G[CS], g_Bt2[CS];
__device__ double g_acc;
__device__ int    g_cnt;

// ---------------- helpers ----------------
__device__ __forceinline__ uint32_t smem_u32(const void* p) {
    uint32_t a;
    asm("{ .reg .u64 t; cvta.to.shared.u64 t, %1; cvt.u32.u64 %0, t; }" : "=r"(a) : "l"(p));
    return a;
}
__device__ __forceinline__ void cp_async16(void* sdst, const void* gsrc) {
    uint32_t s = (uint32_t)__cvta_generic_to_shared(sdst);
    asm volatile("cp.async.cg.shared.global [%0], [%1], 16;\n" :: "r"(s), "l"(gsrc));
}
__device__ __forceinline__ void cp_commit() { asm volatile("cp.async.commit_group;\n"); }

__device__ __forceinline__ void ldsm_x4(uint32_t* r, uint32_t addr) {
    asm volatile("ldmatrix.sync.aligned.m8n8.x4.shared.b16 {%0,%1,%2,%3}, [%4];"
        : "=r"(r[0]), "=r"(r[1]), "=r"(r[2]), "=r"(r[3]) : "r"(addr));
}

__device__ __forceinline__ void mma16816(float* c, const uint32_t* a, const uint32_t* b) {
    asm volatile(
        "mma.sync.aligned.m16n8k16.row.col.f32.bf16.bf16.f32 "
        "{%0,%1,%2,%3}, {%4,%5,%6,%7}, {%8,%9}, {%0,%1,%2,%3};\n"
        : "+f"(c[0]), "+f"(c[1]), "+f"(c[2]), "+f"(c[3])
        : "r"(a[0]), "r"(a[1]), "r"(a[2]), "r"(a[3]), "r"(b[0]), "r"(b[1]));
}

__device__ __forceinline__ uint32_t pack_bf2(float a, float b) {
    __nv_bfloat162 h = __floats2bfloat162_rn(a, b);
    return *reinterpret_cast<uint32_t*>(&h);
}

// ---------------- small prep kernels ----------------
__global__ void zeros_kernel() {
    int i = blockIdx.x * blockDim.x + threadIdx.x;
    if (i < NROWS) { g_s[i] = 0.f; g_s2[i] = 0.f; }
    if (i == 0) { g_acc = 0.0; g_cnt = 0; }
}

// 4 independent uint4 outputs per thread (32 bf16), MLP=8
__global__ void cvt_pred_kernel(const float4* __restrict__ p) {
    size_t base = (size_t)blockIdx.x * 1024 + threadIdx.x;
    float4 v[8];
    #pragma unroll
    for (int k = 0; k < 4; k++) {
        v[2 * k]     = p[2 * (base + 256 * k)];
        v[2 * k + 1] = p[2 * (base + 256 * k) + 1];
    }
    #pragma unroll
    for (int k = 0; k < 4; k++) {
        uint4 o;
        o.x = pack_bf2(v[2 * k].x, v[2 * k].y);
        o.y = pack_bf2(v[2 * k].z, v[2 * k].w);
        o.z = pack_bf2(v[2 * k + 1].x, v[2 * k + 1].y);
        o.w = pack_bf2(v[2 * k + 1].z, v[2 * k + 1].w);
        ((uint4*)g_predb)[base + 256 * k] = o;
    }
}
__global__ void cvt_w1_kernel(const float4* __restrict__ p) {
    size_t base = (size_t)blockIdx.x * 1024 + threadIdx.x;
    float4 v[8];
    #pragma unroll
    for (int k = 0; k < 4; k++) {
        v[2 * k]     = p[2 * (base + 256 * k)];
        v[2 * k + 1] = p[2 * (base + 256 * k) + 1];
    }
    #pragma unroll
    for (int k = 0; k < 4; k++) {
        uint4 o;
        o.x = pack_bf2(v[2 * k].x, v[2 * k].y);
        o.y = pack_bf2(v[2 * k].z, v[2 * k].w);
        o.z = pack_bf2(v[2 * k + 1].x, v[2 * k + 1].y);
        o.w = pack_bf2(v[2 * k + 1].z, v[2 * k + 1].w);
        ((uint4*)g_W1b)[base + 256 * k] = o;
    }
}
// W2g = W2[0:256] * gamma (broadcast over columns)
__global__ void cvt_w2_kernel(const float4* __restrict__ p, const float* __restrict__ gamma) {
    size_t base = (size_t)blockIdx.x * 1024 + threadIdx.x;
    #pragma unroll
    for (int k = 0; k < 4; k++) {
        size_t o_idx = base + 256 * k;
        int c0 = (int)((8 * o_idx) & (TOT - 1));
        float4 v0 = p[2 * o_idx], v1 = p[2 * o_idx + 1];
        uint4 o;
        o.x = pack_bf2(v0.x * __ldg(&gamma[c0]),     v0.y * __ldg(&gamma[c0 + 1]));
        o.y = pack_bf2(v0.z * __ldg(&gamma[c0 + 2]), v0.w * __ldg(&gamma[c0 + 3]));
        o.z = pack_bf2(v1.x * __ldg(&gamma[c0 + 4]), v1.y * __ldg(&gamma[c0 + 5]));
        o.w = pack_bf2(v1.z * __ldg(&gamma[c0 + 6]), v1.w * __ldg(&gamma[c0 + 7]));
        ((uint4*)g_W2b)[o_idx] = o;
    }
}

__global__ void gb_kernel(const float* __restrict__ W2, const float* __restrict__ gamma,
                          const float* __restrict__ beta, const float* __restrict__ b2) {
    int j = blockIdx.x;
    int tid = threadIdx.x, lane = tid & 31, wid = tid >> 5;
    __shared__ float sg[8], sb[8];
    float ag = 0.f, ab = 0.f;
    for (int c = tid; c < TOT; c += 256) {
        float w = W2[(size_t)j * TOT + c];
        ag += gamma[c] * w;
        ab += beta[c] * w;
    }
    #pragma unroll
    for (int off = 16; off; off >>= 1) {
        ag += __shfl_xor_sync(0xffffffffu, ag, off);
        ab += __shfl_xor_sync(0xffffffffu, ab, off);
    }
    if (lane == 0) { sg[wid] = ag; sb[wid] = ab; }
    __syncthreads();
    if (tid == 0) {
        float a = 0.f, b = 0.f;
        for (int w = 0; w < 8; w++) { a += sg[w]; b += sb[w]; }
        g_G[j] = a; g_Bt2[j] = b + b2[j];
    }
}

__global__ void transpose_lt_kernel(const float* __restrict__ ls) {
    __shared__ float t[32][33];
    int o0 = blockIdx.x * 32, v0 = blockIdx.y * 32;
    int tx = threadIdx.x, ty = threadIdx.y;
    #pragma unroll
    for (int k = 0; k < 32; k += 8)
        t[ty + k][tx] = ls[(size_t)(o0 + ty + k) * SELF_IN + (v0 + tx)];
    __syncthreads();
    #pragma unroll
    for (int k = 0; k < 32; k += 8)
        g_LTb[(size_t)(v0 + ty + k) * SELF_OUT + (o0 + tx)] = __float2bfloat16_rn(t[tx][ty + k]);
}

__global__ void count_kernel(const int* __restrict__ idx) {
    int i = blockIdx.x * blockDim.x + threadIdx.x;
    int v = (idx[i] >= 0) ? 1 : 0;
    #pragma unroll
    for (int off = 16; off; off >>= 1) v += __shfl_xor_sync(0xffffffffu, v, off);
    if ((threadIdx.x & 31) == 0) atomicAdd(&g_cnt, v);
}

__global__ void stats_kernel() {
    int r = blockIdx.x * blockDim.x + threadIdx.x;
    if (r < NROWS) {
        float mu  = g_s[r] * (1.f / TOT);
        float var = g_s2[r] * (1.f / TOT) - mu * mu;
        float inv = rsqrtf(var + LN_EPS);
        g_inv[r] = inv;
        g_muinv[r] = mu * inv;
    }
}

__global__ void finalize_kernel(float* out, int out_size) {
    out[0] = (float)g_acc;
    if (out_size > 1) out[1] = (float)g_cnt;
}

// ================= GEMM1: x = relu(pred@W1^T + b1 + self), stats =================
// BM=128 BN=128 BK=64, 3-stage cp.async, ldmatrix, 256 threads (8 warps 4m x 2n)
// Stage pitch 144B/row. smem: As 3x18432 @0, Bs 3x18432 @55296 (end 110592)
// overlay (post-mainloop): LTs 256x136 bf16 @0, sidx @69632, OUT 128x136 bf16 @73728, b1s @108544
#define G1_ST_BYTES 18432
#define G1_BS_OFF   55296
#define G1_LTS_STRIDE 136     // elements; 272B/row (conflict-free: 68 words, 4-bank shift/row)
#define G1_SIDX_OFF 69632
#define G1_OUT_OFF  73728
#define G1_B1_OFF   108544
#define G1_DSMEM    110592

__global__ __launch_bounds__(256, 2) void gemm1_kernel(const int* __restrict__ idx,
                                                       const float* __restrict__ b1) {
    extern __shared__ __align__(128) char sm[];
    const uint32_t smb = smem_u32(sm);
    __nv_bfloat16* LTs = (__nv_bfloat16*)sm;
    int* sidx = (int*)(sm + G1_SIDX_OFF);
    __nv_bfloat16* OUT = (__nv_bfloat16*)(sm + G1_OUT_OFF);
    float* b1s = (float*)(sm + G1_B1_OFF);

    const int tid = threadIdx.x, lane = tid & 31, wid = tid >> 5;
    const int wm = wid & 3, wn = wid >> 2;
    const int m0 = blockIdx.y * 128, n0 = blockIdx.x * 128;

    float acc[2][8][4];
    #pragma unroll
    for (int a = 0; a < 2; a++)
        #pragma unroll
        for (int b = 0; b < 8; b++)
            #pragma unroll
            for (int c = 0; c < 4; c++) acc[a][b][c] = 0.f;

    const __nv_bfloat16* Ag = g_predb + (size_t)m0 * PDIM;
    const __nv_bfloat16* Bg = g_W1b + (size_t)n0 * PDIM;

    auto load_stage = [&](int kt, int st) {
        const int k0 = kt * 64;
        #pragma unroll
        for (int i = 0; i < 4; i++) {
            int q = tid + i * 256, r = q >> 3, c = q & 7;
            cp_async16(sm + st * G1_ST_BYTES + r * 144 + c * 16, Ag + (size_t)r * PDIM + k0 + c * 8);
        }
        #pragma unroll
        for (int i = 0; i < 4; i++) {
            int q = tid + i * 256, r = q >> 3, c = q & 7;
            cp_async16(sm + G1_BS_OFF + st * G1_ST_BYTES + r * 144 + c * 16, Bg + (size_t)r * PDIM + k0 + c * 8);
        }
        cp_commit();
    };

    load_stage(0, 0); load_stage(1, 1);

    const uint32_t offA = smb + ((wm * 32 + (lane & 15)) * 72 + (lane >> 4) * 8) * 2;
    const uint32_t offB = smb + G1_BS_OFF +
        ((wn * 64 + ((lane >> 4) << 3) + (lane & 7)) * 72 + ((lane >> 3) & 1) * 8) * 2;

    const int KT = PDIM / 64; // 8
    for (int kt = 0; kt < KT; kt++) {
        int st = kt % 3;
        if (kt == KT - 1) asm volatile("cp.async.wait_group 0;\n" ::: "memory");
        else              asm volatile("cp.async.wait_group 1;\n" ::: "memory");
        __syncthreads();
        if (kt + 2 < KT) load_stage(kt + 2, (kt + 2) % 3);
        uint32_t aB = offA + st * G1_ST_BYTES;
        uint32_t bB = offB + st * G1_ST_BYTES;
        #pragma unroll
        for (int ks = 0; ks < 4; ks++) {
            uint32_t a[2][4], b[4][4];
            ldsm_x4(a[0], aB + ks * 32);
            ldsm_x4(a[1], aB + ks * 32 + 2304);
            #pragma unroll
            for (int np = 0; np < 4; np++)
                ldsm_x4(b[np], bB + ks * 32 + np * 2304);
            #pragma unroll
            for (int mi = 0; mi < 2; mi++)
                #pragma unroll
                for (int ni = 0; ni < 8; ni++)
                    mma16816(acc[mi][ni], a[mi], &b[ni >> 1][(ni & 1) * 2]);
        }
    }
    __syncthreads();   // mainloop done; safe to overlay stage buffers

    // -------- epilogue phase 1: acc -> OUT (bf16), fill sidx/LTs/b1s --------
    const bool has_self = (n0 >= CS);
    {
        const int lr = lane >> 2, lc = (lane & 3) * 2;
        #pragma unroll
        for (int mi = 0; mi < 2; mi++)
            #pragma unroll
            for (int h = 0; h < 2; h++) {
                int r = wm * 32 + lr + mi * 16 + h * 8;
                #pragma unroll
                for (int ni = 0; ni < 8; ni++) {
                    int c = wn * 64 + ni * 8 + lc;
                    *(__nv_bfloat162*)&OUT[r * G1_LTS_STRIDE + c] =
                        __floats2bfloat162_rn(acc[mi][ni][h * 2], acc[mi][ni][h * 2 + 1]);
                }
            }
    }
    if (tid < 128) {
        b1s[tid] = b1[n0 + tid];
        int vals[8];
        #pragma unroll
        for (int j = 0; j < 8; j++) vals[j] = idx[(size_t)(m0 + tid) * NC + j];
        #pragma unroll
        for (int j = 0; j < 8; j++) {
            int v = vals[j];
            bool dup = false;
            for (int j2 = 0; j2 < j; j2++)
                if (vals[j2] == v) dup = true;
            sidx[tid * 8 + j] = (v >= 0 && v < CS && !dup) ? v : -1;
        }
    }
    if (has_self) {
        int o0 = n0 - CS;
        #pragma unroll
        for (int it = 0; it < 16; it++) {
            int ch = tid + it * 256;
            int v = ch >> 4, c8 = (ch & 15) * 8;
            *(uint4*)&LTs[v * G1_LTS_STRIDE + c8] =
                *(const uint4*)&g_LTb[(size_t)v * SELF_OUT + o0 + c8];
        }
    }
    __syncthreads();

    // -------- epilogue phase 2: row-major pass (half-warp per row) --------
    // thread: c16 = tid&15 (16B chunk), row group rb = tid>>4; 8 passes cover 128 rows
    {
        const int c16 = tid & 15, rb = tid >> 4;
        float b1v[8];
        #pragma unroll
        for (int e = 0; e < 8; e++) b1v[e] = b1s[c16 * 8 + e];

        #pragma unroll
        for (int p = 0; p < 8; p++) {
            const int r = rb + p * 16;
            const int grow = m0 + r;
            uint4 w = *(const uint4*)&OUT[r * G1_LTS_STRIDE + c16 * 8];
            float x[8];
            {
                const __nv_bfloat162* h2 = (const __nv_bfloat162*)&w;
                #pragma unroll
                for (int e = 0; e < 4; e++) {
                    float2 f2 = __bfloat1622float2(h2[e]);
                    x[2 * e]     = f2.x + b1v[2 * e];
                    x[2 * e + 1] = f2.y + b1v[2 * e + 1];
                }
            }
            if (has_self) {
                #pragma unroll
                for (int j = 0; j < 8; j++) {
                    int v = sidx[r * 8 + j];
                    if (v < 0) continue;
                    uint4 g = *(const uint4*)&LTs[v * G1_LTS_STRIDE + c16 * 8];
                    const __nv_bfloat162* h2 = (const __nv_bfloat162*)&g;
                    #pragma unroll
                    for (int e = 0; e < 4; e++) {
                        float2 f2 = __bfloat1622float2(h2[e]);
                        x[2 * e]     += f2.x;
                        x[2 * e + 1] += f2.y;
                    }
                }
            }
            float s = 0.f, s2 = 0.f;
            #pragma unroll
            for (int e = 0; e < 8; e++) {
                x[e] = fmaxf(x[e], 0.f);
                s += x[e]; s2 += x[e] * x[e];
            }
            // coalesced store: half-warp covers 256B row segment
            uint4 o;
            o.x = pack_bf2(x[0], x[1]); o.y = pack_bf2(x[2], x[3]);
            o.z = pack_bf2(x[4], x[5]); o.w = pack_bf2(x[6], x[7]);
            *(uint4*)&g_hidden[(size_t)grow * TOT + n0 + c16 * 8] = o;
            // reduce over 16 lanes (stays within half-warp: xor of bits 0..3)
            #pragma unroll
            for (int off = 8; off; off >>= 1) {
                s  += __shfl_xor_sync(0xffffffffu, s, off);
                s2 += __shfl_xor_sync(0xffffffffu, s2, off);
            }
            if ((lane & 15) == 0) {
                atomicAdd(&g_s[grow], s);
                atomicAdd(&g_s2[grow], s2);
            }
        }
    }
}

// ================= GEMM2 + LN fold + log-softmax + gather-reduce =================
// BM=64 BN=256 BK=32, 3-stage, ldmatrix, 256 threads (8 warps 2m x 4n)
// smem: As 3x5120B @0, Bs 3x20480B @15360; overlay: Ls 64x260 f32 @0; red @76800
#define G2_BS_OFF 15360
#define G2_RED_OFF 76800
#define G2_DSMEM   76832

__global__ __launch_bounds__(256, 2) void gemm2_kernel(const int* __restrict__ idx) {
    extern __shared__ __align__(128) char sm[];
    const uint32_t smb = smem_u32(sm);
    float* Ls = (float*)sm;
    float* sred = (float*)(sm + G2_RED_OFF);

    const int tid = threadIdx.x, lane = tid & 31, wid = tid >> 5;
    const int wm = wid & 1, wn = wid >> 1;
    const int m0 = blockIdx.x * 64;

    float acc[2][8][4];
    #pragma unroll
    for (int a = 0; a < 2; a++)
        #pragma unroll
        for (int b = 0; b < 8; b++)
            #pragma unroll
            for (int c = 0; c < 4; c++) acc[a][b][c] = 0.f;

    const __nv_bfloat16* Ag = g_hidden + (size_t)m0 * TOT;
    const __nv_bfloat16* Bg = g_W2b;

    auto load_stage = [&](int kt, int st) {
        const int k0 = kt * 32;
        {
            int r = tid >> 2, c = tid & 3;
            cp_async16(sm + st * 5120 + r * 80 + c * 16, Ag + (size_t)r * TOT + k0 + c * 8);
        }
        #pragma unroll
        for (int i = 0; i < 4; i++) {
            int q = tid + i * 256, r = q >> 2, c = q & 3;
            cp_async16(sm + G2_BS_OFF + st * 20480 + r * 80 + c * 16, Bg + (size_t)r * TOT + k0 + c * 8);
        }
        cp_commit();
    };

    load_stage(0, 0); load_stage(1, 1);

    const uint32_t offA = smb + ((wm * 32 + (lane & 15)) * 40 + (lane >> 4) * 8) * 2;
    const uint32_t offB = smb + G2_BS_OFF +
        ((wn * 64 + ((lane >> 4) << 3) + (lane & 7)) * 40 + ((lane >> 3) & 1) * 8) * 2;

    const int KT = TOT / 32;  // 64
    for (int kt = 0; kt < KT; kt++) {
        int st = kt % 3;
        if (kt == KT - 1) asm volatile("cp.async.wait_group 0;\n" ::: "memory");
        else              asm volatile("cp.async.wait_group 1;\n" ::: "memory");
        __syncthreads();
        if (kt + 2 < KT) load_stage(kt + 2, (kt + 2) % 3);
        uint32_t aB = offA + st * 5120;
        uint32_t bB = offB + st * 20480;
        #pragma unroll
        for (int ks = 0; ks < 2; ks++) {
            uint32_t a[2][4], b[4][4];
            ldsm_x4(a[0], aB + ks * 32);
            ldsm_x4(a[1], aB + ks * 32 + 1280);
            #pragma unroll
            for (int np = 0; np < 4; np++)
                ldsm_x4(b[np], bB + ks * 32 + np * 1280);
            #pragma unroll
            for (int mi = 0; mi < 2; mi++)
                #pragma unroll
                for (int ni = 0; ni < 8; ni++)
                    mma16816(acc[mi][ni], a[mi], &b[ni >> 1][(ni & 1) * 2]);
        }
    }
    __syncthreads();

    // stage logits into smem with LN affine folded: logit = acc*inv - muinv*G[c] + Bt2[c]
    {
        int r0 = wm * 32 + (lane >> 2);
        int c0 = wn * 64 + (lane & 3) * 2;
        #pragma unroll
        for (int mi = 0; mi < 2; mi++) {
            #pragma unroll
            for (int h = 0; h < 2; h++) {
                int r = r0 + mi * 16 + h * 8;
                float inv = __ldg(&g_inv[m0 + r]);
                float mui = __ldg(&g_muinv[m0 + r]);
                #pragma unroll
                for (int ni = 0; ni < 8; ni++) {
                    int c = c0 + ni * 8;
                    float g0 = __ldg(&g_G[c]),   g1 = __ldg(&g_G[c + 1]);
                    float t0 = __ldg(&g_Bt2[c]), t1 = __ldg(&g_Bt2[c + 1]);
                    Ls[r * 260 + c]     = acc[mi][ni][h * 2]     * inv - mui * g0 + t0;
                    Ls[r * 260 + c + 1] = acc[mi][ni][h * 2 + 1] * inv - mui * g1 + t1;
                }
            }
        }
    }
    __syncthreads();

    // per-row logsumexp + gather (4 threads/row, interleaved columns -> conflict-free)
    int row = tid >> 2, sub = tid & 3;
    const float* Lr = Ls + row * 260;
    float m = -1e30f;
    #pragma unroll
    for (int i = 0; i < 64; i++) m = fmaxf(m, Lr[sub + i * 4]);
    m = fmaxf(m, __shfl_xor_sync(0xffffffffu, m, 1));
    m = fmaxf(m, __shfl_xor_sync(0xffffffffu, m, 2));
    float se = 0.f;
    #pragma unroll
    for (int i = 0; i < 64; i++) se += __expf(Lr[sub + i * 4] - m);
    se += __shfl_xor_sync(0xffffffffu, se, 1);
    se += __shfl_xor_sync(0xffffffffu, se, 2);
    float lse = m + logf(se);

    float contrib = 0.f;
    if (sub == 0) {
        int gn = m0 + row;
        int vals[8];
        #pragma unroll
        for (int j = 0; j < 8; j++) vals[j] = idx[(size_t)gn * NC + j];
        float a = 0.f; int cnt = 0;
        #pragma unroll
        for (int j = 0; j < 8; j++) {
            int vv = vals[j];
            if (vv < 0 || vv >= CS) continue;
            bool dup = false;
            for (int j2 = 0; j2 < j; j2++)
                if (vals[j2] == vv) dup = true;
            if (dup) continue;
            a += Lr[vv]; cnt++;
        }
        contrib = a - (float)cnt * lse;
    }
    #pragma unroll
    for (int off = 16; off; off >>= 1) contrib += __shfl_xor_sync(0xffffffffu, contrib, off);
    if (lane == 0) sred[wid] = contrib;
    __syncthreads();
    if (tid == 0) {
        float t = 0.f;
        for (int w = 0; w < 8; w++) t += sred[w];
        atomicAdd(&g_acc, (double)t);
    }
}

// ---------------- launcher ----------------
extern "C" void kernel_launch(void* const* d_in, const int* in_sizes, int n_in,
                              void* d_out, int out_size) {
    const float* pred  = (const float*)d_in[0];
    const int*   idx   = (const int*)  d_in[1];
    const float* W1    = (const float*)d_in[2];
    const float* b1    = (const float*)d_in[3];
    const float* ls    = (const float*)d_in[4];
    const float* gamma = (const float*)d_in[5];
    const float* beta  = (const float*)d_in[6];
    const float* W2    = (const float*)d_in[7];
    const float* b2    = (const float*)d_in[8];
    float* out = (float*)d_out;

    cudaFuncSetAttribute(gemm1_kernel, cudaFuncAttributeMaxDynamicSharedMemorySize, G1_DSMEM);
    cudaFuncSetAttribute(gemm2_kernel, cudaFuncAttributeMaxDynamicSharedMemorySize, G2_DSMEM);

    cvt_pred_kernel<<<(NROWS * PDIM / 8) / 1024, 256>>>((const float4*)pred);
    cvt_w1_kernel<<<(TOT * PDIM / 8) / 1024, 256>>>((const float4*)W1);
    transpose_lt_kernel<<<dim3(SELF_OUT / 32, CS / 32), dim3(32, 8)>>>(ls);
    zeros_kernel<<<NROWS / 256, 256>>>();
    count_kernel<<<(NROWS * NC) / 256, 256>>>(idx);

    gemm1_kernel<<<dim3(TOT / 128, NROWS / 128), 256, G1_DSMEM>>>(idx, b1);

    cvt_w2_kernel<<<(CS * TOT / 8) / 1024, 256>>>((const float4*)W2, gamma);
    gb_kernel<<<CS, 256>>>(W2, gamma, beta, b2);
    stats_kernel<<<NROWS / 256, 256>>>();

    gemm2_kernel<<<NROWS / 64, 256, G2_DSMEM>>>(idx);

    finalize_kernel<<<1, 1>>>(out, out_size);
}

// round 14
// speedup vs baseline: 2.2135x; 1.0550x over previous
#include <cuda_runtime.h>
#include <cuda_bf16.h>
#include <cstdint>

// Problem constants
#define NROWS 32768        // B*T
#define PDIM  512
#define NC    8
#define CS    256
#define TOT   2048         // NC*CS
#define SELF_OUT 1792
#define SELF_IN  1792
#define LN_EPS 1e-5f

// ---------------- device scratch (allocation-free rule) ----------------
__device__ __nv_bfloat16 g_predb[(size_t)NROWS * PDIM];        // 32 MB
__device__ __nv_bfloat16 g_W1b[(size_t)TOT * PDIM];            // 2 MB
__device__ __nv_bfloat16 g_W2b[(size_t)CS * TOT];              // 1 MB  W2g = W2[0:256]*gamma
__device__ __nv_bfloat16 g_LTb[(size_t)CS * SELF_OUT];         // LT[v][o] = linear_self[o][v]
__device__ __nv_bfloat16 g_hidden[(size_t)NROWS * TOT];        // 128 MB (post-relu x)
__device__ float g_s[NROWS], g_s2[NROWS];
__device__ float g_inv[NROWS], g_muinv[NROWS];
__device__ float g_G[CS], g_Bt2[CS];
__device__ double g_acc;
__device__ int    g_cnt;

// ---------------- helpers ----------------
__device__ __forceinline__ uint32_t smem_u32(const void* p) {
    uint32_t a;
    asm("{ .reg .u64 t; cvta.to.shared.u64 t, %1; cvt.u32.u64 %0, t; }" : "=r"(a) : "l"(p));
    return a;
}
__device__ __forceinline__ void cp_async16(void* sdst, const void* gsrc) {
    uint32_t s = (uint32_t)__cvta_generic_to_shared(sdst);
    asm volatile("cp.async.cg.shared.global [%0], [%1], 16;\n" :: "r"(s), "l"(gsrc));
}
__device__ __forceinline__ void cp_commit() { asm volatile("cp.async.commit_group;\n"); }

__device__ __forceinline__ void ldsm_x4(uint32_t* r, uint32_t addr) {
    asm volatile("ldmatrix.sync.aligned.m8n8.x4.shared.b16 {%0,%1,%2,%3}, [%4];"
        : "=r"(r[0]), "=r"(r[1]), "=r"(r[2]), "=r"(r[3]) : "r"(addr));
}

__device__ __forceinline__ void mma16816(float* c, const uint32_t* a, const uint32_t* b) {
    asm volatile(
        "mma.sync.aligned.m16n8k16.row.col.f32.bf16.bf16.f32 "
        "{%0,%1,%2,%3}, {%4,%5,%6,%7}, {%8,%9}, {%0,%1,%2,%3};\n"
        : "+f"(c[0]), "+f"(c[1]), "+f"(c[2]), "+f"(c[3])
        : "r"(a[0]), "r"(a[1]), "r"(a[2]), "r"(a[3]), "r"(b[0]), "r"(b[1]));
}

__device__ __forceinline__ uint32_t pack_bf2(float a, float b) {
    __nv_bfloat162 h = __floats2bfloat162_rn(a, b);
    return *reinterpret_cast<uint32_t*>(&h);
}

// ---------------- small prep kernels ----------------
__global__ void zeros_kernel() {
    int i = blockIdx.x * blockDim.x + threadIdx.x;
    if (i < NROWS) { g_s[i] = 0.f; g_s2[i] = 0.f; }
    if (i == 0) { g_acc = 0.0; g_cnt = 0; }
}

// counts valid codebook entries (8 idx per thread); separate launch AFTER zeros
__global__ void count_kernel(const int* __restrict__ idx) {
    int i = blockIdx.x * blockDim.x + threadIdx.x;
    int c = 0;
    #pragma unroll
    for (int j = 0; j < 8; j++) c += (idx[i * 8 + j] >= 0) ? 1 : 0;
    #pragma unroll
    for (int off = 16; off; off >>= 1) c += __shfl_xor_sync(0xffffffffu, c, off);
    if ((threadIdx.x & 31) == 0) atomicAdd(&g_cnt, c);
}

// 4 independent uint4 outputs per thread (32 bf16), MLP=8
__global__ void cvt_pred_kernel(const float4* __restrict__ p) {
    size_t base = (size_t)blockIdx.x * 1024 + threadIdx.x;
    float4 v[8];
    #pragma unroll
    for (int k = 0; k < 4; k++) {
        v[2 * k]     = p[2 * (base + 256 * k)];
        v[2 * k + 1] = p[2 * (base + 256 * k) + 1];
    }
    #pragma unroll
    for (int k = 0; k < 4; k++) {
        uint4 o;
        o.x = pack_bf2(v[2 * k].x, v[2 * k].y);
        o.y = pack_bf2(v[2 * k].z, v[2 * k].w);
        o.z = pack_bf2(v[2 * k + 1].x, v[2 * k + 1].y);
        o.w = pack_bf2(v[2 * k + 1].z, v[2 * k + 1].w);
        ((uint4*)g_predb)[base + 256 * k] = o;
    }
}
__global__ void cvt_w1_kernel(const float4* __restrict__ p) {
    size_t base = (size_t)blockIdx.x * 1024 + threadIdx.x;
    float4 v[8];
    #pragma unroll
    for (int k = 0; k < 4; k++) {
        v[2 * k]     = p[2 * (base + 256 * k)];
        v[2 * k + 1] = p[2 * (base + 256 * k) + 1];
    }
    #pragma unroll
    for (int k = 0; k < 4; k++) {
        uint4 o;
        o.x = pack_bf2(v[2 * k].x, v[2 * k].y);
        o.y = pack_bf2(v[2 * k].z, v[2 * k].w);
        o.z = pack_bf2(v[2 * k + 1].x, v[2 * k + 1].y);
        o.w = pack_bf2(v[2 * k + 1].z, v[2 * k + 1].w);
        ((uint4*)g_W1b)[base + 256 * k] = o;
    }
}
// W2g = W2[0:256] * gamma (broadcast over columns)
__global__ void cvt_w2_kernel(const float4* __restrict__ p, const float* __restrict__ gamma) {
    size_t base = (size_t)blockIdx.x * 1024 + threadIdx.x;
    #pragma unroll
    for (int k = 0; k < 4; k++) {
        size_t o_idx = base + 256 * k;
        int c0 = (int)((8 * o_idx) & (TOT - 1));
        float4 v0 = p[2 * o_idx], v1 = p[2 * o_idx + 1];
        uint4 o;
        o.x = pack_bf2(v0.x * __ldg(&gamma[c0]),     v0.y * __ldg(&gamma[c0 + 1]));
        o.y = pack_bf2(v0.z * __ldg(&gamma[c0 + 2]), v0.w * __ldg(&gamma[c0 + 3]));
        o.z = pack_bf2(v1.x * __ldg(&gamma[c0 + 4]), v1.y * __ldg(&gamma[c0 + 5]));
        o.w = pack_bf2(v1.z * __ldg(&gamma[c0 + 6]), v1.w * __ldg(&gamma[c0 + 7]));
        ((uint4*)g_W2b)[o_idx] = o;
    }
}

__global__ void gb_kernel(const float* __restrict__ W2, const float* __restrict__ gamma,
                          const float* __restrict__ beta, const float* __restrict__ b2) {
    int j = blockIdx.x;
    int tid = threadIdx.x, lane = tid & 31, wid = tid >> 5;
    __shared__ float sg[8], sb[8];
    float ag = 0.f, ab = 0.f;
    for (int c = tid; c < TOT; c += 256) {
        float w = W2[(size_t)j * TOT + c];
        ag += gamma[c] * w;
        ab += beta[c] * w;
    }
    #pragma unroll
    for (int off = 16; off; off >>= 1) {
        ag += __shfl_xor_sync(0xffffffffu, ag, off);
        ab += __shfl_xor_sync(0xffffffffu, ab, off);
    }
    if (lane == 0) { sg[wid] = ag; sb[wid] = ab; }
    __syncthreads();
    if (tid == 0) {
        float a = 0.f, b = 0.f;
        for (int w = 0; w < 8; w++) { a += sg[w]; b += sb[w]; }
        g_G[j] = a; g_Bt2[j] = b + b2[j];
    }
}

__global__ void transpose_lt_kernel(const float* __restrict__ ls) {
    __shared__ float t[32][33];
    int o0 = blockIdx.x * 32, v0 = blockIdx.y * 32;
    int tx = threadIdx.x, ty = threadIdx.y;
    #pragma unroll
    for (int k = 0; k < 32; k += 8)
        t[ty + k][tx] = ls[(size_t)(o0 + ty + k) * SELF_IN + (v0 + tx)];
    __syncthreads();
    #pragma unroll
    for (int k = 0; k < 32; k += 8)
        g_LTb[(size_t)(v0 + ty + k) * SELF_OUT + (o0 + tx)] = __float2bfloat16_rn(t[tx][ty + k]);
}

__global__ void stats_kernel() {
    int r = blockIdx.x * blockDim.x + threadIdx.x;
    if (r < NROWS) {
        float mu  = g_s[r] * (1.f / TOT);
        float var = g_s2[r] * (1.f / TOT) - mu * mu;
        float inv = rsqrtf(var + LN_EPS);
        g_inv[r] = inv;
        g_muinv[r] = mu * inv;
    }
}

__global__ void finalize_kernel(float* out, int out_size) {
    out[0] = (float)g_acc;
    if (out_size > 1) out[1] = (float)g_cnt;
}

// ================= GEMM1: x = relu(pred@W1^T + b1 + self), stats =================
// BM=128 BN=128 BK=64, 3-stage cp.async, ldmatrix, 256 threads (8 warps 4m x 2n)
// Stage pitch 144B/row. smem: As 3x18432 @0, Bs 3x18432 @55296 (end 110592)
// overlay (post-mainloop): LTs 256x136 bf16 @0, sidx @69632, OUT 128x136 bf16 @73728, b1s @108544
#define G1_ST_BYTES 18432
#define G1_BS_OFF   55296
#define G1_LTS_STRIDE 136
#define G1_SIDX_OFF 69632
#define G1_OUT_OFF  73728
#define G1_B1_OFF   108544
#define G1_DSMEM    110592

__global__ __launch_bounds__(256, 2) void gemm1_kernel(const int* __restrict__ idx,
                                                       const float* __restrict__ b1) {
    extern __shared__ __align__(128) char sm[];
    const uint32_t smb = smem_u32(sm);
    __nv_bfloat16* LTs = (__nv_bfloat16*)sm;
    int* sidx = (int*)(sm + G1_SIDX_OFF);
    __nv_bfloat16* OUT = (__nv_bfloat16*)(sm + G1_OUT_OFF);
    float* b1s = (float*)(sm + G1_B1_OFF);

    const int tid = threadIdx.x, lane = tid & 31, wid = tid >> 5;
    const int wm = wid & 3, wn = wid >> 2;
    const int m0 = blockIdx.y * 128, n0 = blockIdx.x * 128;

    float acc[2][8][4];
    #pragma unroll
    for (int a = 0; a < 2; a++)
        #pragma unroll
        for (int b = 0; b < 8; b++)
            #pragma unroll
            for (int c = 0; c < 4; c++) acc[a][b][c] = 0.f;

    const __nv_bfloat16* Ag = g_predb + (size_t)m0 * PDIM;
    const __nv_bfloat16* Bg = g_W1b + (size_t)n0 * PDIM;

    auto load_stage = [&](int kt, int st) {
        const int k0 = kt * 64;
        #pragma unroll
        for (int i = 0; i < 4; i++) {
            int q = tid + i * 256, r = q >> 3, c = q & 7;
            cp_async16(sm + st * G1_ST_BYTES + r * 144 + c * 16, Ag + (size_t)r * PDIM + k0 + c * 8);
        }
        #pragma unroll
        for (int i = 0; i < 4; i++) {
            int q = tid + i * 256, r = q >> 3, c = q & 7;
            cp_async16(sm + G1_BS_OFF + st * G1_ST_BYTES + r * 144 + c * 16, Bg + (size_t)r * PDIM + k0 + c * 8);
        }
        cp_commit();
    };

    load_stage(0, 0); load_stage(1, 1);

    const uint32_t offA = smb + ((wm * 32 + (lane & 15)) * 72 + (lane >> 4) * 8) * 2;
    const uint32_t offB = smb + G1_BS_OFF +
        ((wn * 64 + ((lane >> 4) << 3) + (lane & 7)) * 72 + ((lane >> 3) & 1) * 8) * 2;

    const int KT = PDIM / 64; // 8
    for (int kt = 0; kt < KT; kt++) {
        int st = kt % 3;
        if (kt == KT - 1) asm volatile("cp.async.wait_group 0;\n" ::: "memory");
        else              asm volatile("cp.async.wait_group 1;\n" ::: "memory");
        __syncthreads();
        if (kt + 2 < KT) load_stage(kt + 2, (kt + 2) % 3);
        uint32_t aB = offA + st * G1_ST_BYTES;
        uint32_t bB = offB + st * G1_ST_BYTES;
        #pragma unroll
        for (int ks = 0; ks < 4; ks++) {
            uint32_t a[2][4], b[4][4];
            ldsm_x4(a[0], aB + ks * 32);
            ldsm_x4(a[1], aB + ks * 32 + 2304);
            #pragma unroll
            for (int np = 0; np < 4; np++)
                ldsm_x4(b[np], bB + ks * 32 + np * 2304);
            #pragma unroll
            for (int mi = 0; mi < 2; mi++)
                #pragma unroll
                for (int ni = 0; ni < 8; ni++)
                    mma16816(acc[mi][ni], a[mi], &b[ni >> 1][(ni & 1) * 2]);
        }
    }
    __syncthreads();   // mainloop done; safe to overlay stage buffers

    // -------- epilogue phase 1: acc -> OUT (bf16), fill sidx/LTs/b1s --------
    const bool has_self = (n0 >= CS);
    {
        const int lr = lane >> 2, lc = (lane & 3) * 2;
        #pragma unroll
        for (int mi = 0; mi < 2; mi++)
            #pragma unroll
            for (int h = 0; h < 2; h++) {
                int r = wm * 32 + lr + mi * 16 + h * 8;
                #pragma unroll
                for (int ni = 0; ni < 8; ni++) {
                    int c = wn * 64 + ni * 8 + lc;
                    *(__nv_bfloat162*)&OUT[r * G1_LTS_STRIDE + c] =
                        __floats2bfloat162_rn(acc[mi][ni][h * 2], acc[mi][ni][h * 2 + 1]);
                }
            }
    }
    if (tid < 128) {
        b1s[tid] = b1[n0 + tid];
        int vals[8];
        #pragma unroll
        for (int j = 0; j < 8; j++) vals[j] = idx[(size_t)(m0 + tid) * NC + j];
        #pragma unroll
        for (int j = 0; j < 8; j++) {
            int v = vals[j];
            bool dup = false;
            for (int j2 = 0; j2 < j; j2++)
                if (vals[j2] == v) dup = true;
            sidx[tid * 8 + j] = (v >= 0 && v < CS && !dup) ? v : -1;
        }
    }
    if (has_self) {
        int o0 = n0 - CS;
        #pragma unroll
        for (int it = 0; it < 16; it++) {
            int ch = tid + it * 256;
            int v = ch >> 4, c8 = (ch & 15) * 8;
            *(uint4*)&LTs[v * G1_LTS_STRIDE + c8] =
                *(const uint4*)&g_LTb[(size_t)v * SELF_OUT + o0 + c8];
        }
    }
    __syncthreads();

    // -------- epilogue phase 2: row-major pass (half-warp per row) --------
    {
        const int c16 = tid & 15, rb = tid >> 4;
        float b1v[8];
        #pragma unroll
        for (int e = 0; e < 8; e++) b1v[e] = b1s[c16 * 8 + e];

        #pragma unroll
        for (int p = 0; p < 8; p++) {
            const int r = rb + p * 16;
            const int grow = m0 + r;
            uint4 w = *(const uint4*)&OUT[r * G1_LTS_STRIDE + c16 * 8];
            float x[8];
            {
                const __nv_bfloat162* h2 = (const __nv_bfloat162*)&w;
                #pragma unroll
                for (int e = 0; e < 4; e++) {
                    float2 f2 = __bfloat1622float2(h2[e]);
                    x[2 * e]     = f2.x + b1v[2 * e];
                    x[2 * e + 1] = f2.y + b1v[2 * e + 1];
                }
            }
            if (has_self) {
                #pragma unroll
                for (int j = 0; j < 8; j++) {
                    int v = sidx[r * 8 + j];
                    if (v < 0) continue;
                    uint4 g = *(const uint4*)&LTs[v * G1_LTS_STRIDE + c16 * 8];
                    const __nv_bfloat162* h2 = (const __nv_bfloat162*)&g;
                    #pragma unroll
                    for (int e = 0; e < 4; e++) {
                        float2 f2 = __bfloat1622float2(h2[e]);
                        x[2 * e]     += f2.x;
                        x[2 * e + 1] += f2.y;
                    }
                }
            }
            float s = 0.f, s2 = 0.f;
            #pragma unroll
            for (int e = 0; e < 8; e++) {
                x[e] = fmaxf(x[e], 0.f);
                s += x[e]; s2 += x[e] * x[e];
            }
            uint4 o;
            o.x = pack_bf2(x[0], x[1]); o.y = pack_bf2(x[2], x[3]);
            o.z = pack_bf2(x[4], x[5]); o.w = pack_bf2(x[6], x[7]);
            *(uint4*)&g_hidden[(size_t)grow * TOT + n0 + c16 * 8] = o;
            #pragma unroll
            for (int off = 8; off; off >>= 1) {
                s  += __shfl_xor_sync(0xffffffffu, s, off);
                s2 += __shfl_xor_sync(0xffffffffu, s2, off);
            }
            if ((lane & 15) == 0) {
                atomicAdd(&g_s[grow], s);
                atomicAdd(&g_s2[grow], s2);
            }
        }
    }
}

// ================= GEMM2 + LN fold + log-softmax + gather-reduce =================
// BM=64 BN=256 BK=64, 2-stage, ldmatrix, 256 threads (8 warps 2m x 4n)
// Stage pitch 144B/row (conflict-free LDSM). A stage 9216B, B stage 36864B.
// smem: As 2x9216 @0, Bs 2x36864 @18432 (end 92160)
// overlay: Ls 64x260 f32 @0 (66560); red @92160
#define G2_ST_A   9216
#define G2_ST_B   36864
#define G2_BS_OFF 18432
#define G2_RED_OFF 92160
#define G2_DSMEM   92192

__global__ __launch_bounds__(256, 2) void gemm2_kernel(const int* __restrict__ idx) {
    extern __shared__ __align__(128) char sm[];
    const uint32_t smb = smem_u32(sm);
    float* Ls = (float*)sm;
    float* sred = (float*)(sm + G2_RED_OFF);

    const int tid = threadIdx.x, lane = tid & 31, wid = tid >> 5;
    const int wm = wid & 1, wn = wid >> 1;
    const int m0 = blockIdx.x * 64;

    float acc[2][8][4];
    #pragma unroll
    for (int a = 0; a < 2; a++)
        #pragma unroll
        for (int b = 0; b < 8; b++)
            #pragma unroll
            for (int c = 0; c < 4; c++) acc[a][b][c] = 0.f;

    const __nv_bfloat16* Ag = g_hidden + (size_t)m0 * TOT;
    const __nv_bfloat16* Bg = g_W2b;

    auto load_stage = [&](int kt, int st) {
        const int k0 = kt * 64;
        #pragma unroll
        for (int i = 0; i < 2; i++) {
            int q = tid + i * 256, r = q >> 3, c = q & 7;
            cp_async16(sm + st * G2_ST_A + r * 144 + c * 16, Ag + (size_t)r * TOT + k0 + c * 8);
        }
        #pragma unroll
        for (int i = 0; i < 8; i++) {
            int q = tid + i * 256, r = q >> 3, c = q & 7;
            cp_async16(sm + G2_BS_OFF + st * G2_ST_B + r * 144 + c * 16, Bg + (size_t)r * TOT + k0 + c * 8);
        }
        cp_commit();
    };

    load_stage(0, 0);

    const uint32_t offA = smb + ((wm * 32 + (lane & 15)) * 72 + (lane >> 4) * 8) * 2;
    const uint32_t offB = smb + G2_BS_OFF +
        ((wn * 64 + ((lane >> 4) << 3) + (lane & 7)) * 72 + ((lane >> 3) & 1) * 8) * 2;

    const int KT = TOT / 64;  // 32
    for (int kt = 0; kt < KT; kt++) {
        int st = kt & 1;
        asm volatile("cp.async.wait_group 0;\n" ::: "memory");
        __syncthreads();
        if (kt + 1 < KT) load_stage(kt + 1, st ^ 1);   // overlaps compute below
        uint32_t aB = offA + st * G2_ST_A;
        uint32_t bB = offB + st * G2_ST_B;
        #pragma unroll
        for (int ks = 0; ks < 4; ks++) {
            uint32_t a[2][4], b[4][4];
            ldsm_x4(a[0], aB + ks * 32);
            ldsm_x4(a[1], aB + ks * 32 + 2304);
            #pragma unroll
            for (int np = 0; np < 4; np++)
                ldsm_x4(b[np], bB + ks * 32 + np * 2304);
            #pragma unroll
            for (int mi = 0; mi < 2; mi++)
                #pragma unroll
                for (int ni = 0; ni < 8; ni++)
                    mma16816(acc[mi][ni], a[mi], &b[ni >> 1][(ni & 1) * 2]);
        }
    }
    __syncthreads();

    // stage logits into smem with LN affine folded: logit = acc*inv - muinv*G[c] + Bt2[c]
    {
        int r0 = wm * 32 + (lane >> 2);
        int c0 = wn * 64 + (lane & 3) * 2;
        #pragma unroll
        for (int mi = 0; mi < 2; mi++) {
            #pragma unroll
            for (int h = 0; h < 2; h++) {
                int r = r0 + mi * 16 + h * 8;
                float inv = __ldg(&g_inv[m0 + r]);
                float mui = __ldg(&g_muinv[m0 + r]);
                #pragma unroll
                for (int ni = 0; ni < 8; ni++) {
                    int c = c0 + ni * 8;
                    float g0 = __ldg(&g_G[c]),   g1 = __ldg(&g_G[c + 1]);
                    float t0 = __ldg(&g_Bt2[c]), t1 = __ldg(&g_Bt2[c + 1]);
                    Ls[r * 260 + c]     = acc[mi][ni][h * 2]     * inv - mui * g0 + t0;
                    Ls[r * 260 + c + 1] = acc[mi][ni][h * 2 + 1] * inv - mui * g1 + t1;
                }
            }
        }
    }
    __syncthreads();

    // per-row logsumexp + gather (4 threads/row, interleaved columns -> conflict-free)
    int row = tid >> 2, sub = tid & 3;
    const float* Lr = Ls + row * 260;
    float m = -1e30f;
    #pragma unroll
    for (int i = 0; i < 64; i++) m = fmaxf(m, Lr[sub + i * 4]);
    m = fmaxf(m, __shfl_xor_sync(0xffffffffu, m, 1));
    m = fmaxf(m, __shfl_xor_sync(0xffffffffu, m, 2));
    float se = 0.f;
    #pragma unroll
    for (int i = 0; i < 64; i++) se += __expf(Lr[sub + i * 4] - m);
    se += __shfl_xor_sync(0xffffffffu, se, 1);
    se += __shfl_xor_sync(0xffffffffu, se, 2);
    float lse = m + logf(se);

    float contrib = 0.f;
    if (sub == 0) {
        int gn = m0 + row;
        int vals[8];
        #pragma unroll
        for (int j = 0; j < 8; j++) vals[j] = idx[(size_t)gn * NC + j];
        float a = 0.f; int cnt = 0;
        #pragma unroll
        for (int j = 0; j < 8; j++) {
            int vv = vals[j];
            if (vv < 0 || vv >= CS) continue;
            bool dup = false;
            for (int j2 = 0; j2 < j; j2++)
                if (vals[j2] == vv) dup = true;
            if (dup) continue;
            a += Lr[vv]; cnt++;
        }
        contrib = a - (float)cnt * lse;
    }
    #pragma unroll
    for (int off = 16; off; off >>= 1) contrib += __shfl_xor_sync(0xffffffffu, contrib, off);
    if (lane == 0) sred[wid] = contrib;
    __syncthreads();
    if (tid == 0) {
        float t = 0.f;
        for (int w = 0; w < 8; w++) t += sred[w];
        atomicAdd(&g_acc, (double)t);
    }
}

// ---------------- launcher ----------------
extern "C" void kernel_launch(void* const* d_in, const int* in_sizes, int n_in,
                              void* d_out, int out_size) {
    const float* pred  = (const float*)d_in[0];
    const int*   idx   = (const int*)  d_in[1];
    const float* W1    = (const float*)d_in[2];
    const float* b1    = (const float*)d_in[3];
    const float* ls    = (const float*)d_in[4];
    const float* gamma = (const float*)d_in[5];
    const float* beta  = (const float*)d_in[6];
    const float* W2    = (const float*)d_in[7];
    const float* b2    = (const float*)d_in[8];
    float* out = (float*)d_out;

    cudaFuncSetAttribute(gemm1_kernel, cudaFuncAttributeMaxDynamicSharedMemorySize, G1_DSMEM);
    cudaFuncSetAttribute(gemm2_kernel, cudaFuncAttributeMaxDynamicSharedMemorySize, G2_DSMEM);

    zeros_kernel<<<NROWS / 256, 256>>>();
    cvt_pred_kernel<<<(NROWS * PDIM / 8) / 1024, 256>>>((const float4*)pred);
    cvt_w1_kernel<<<(TOT * PDIM / 8) / 1024, 256>>>((const float4*)W1);
    transpose_lt_kernel<<<dim3(SELF_OUT / 32, CS / 32), dim3(32, 8)>>>(ls);
    count_kernel<<<NROWS / 256, 256>>>(idx);

    gemm1_kernel<<<dim3(TOT / 128, NROWS / 128), 256, G1_DSMEM>>>(idx, b1);

    cvt_w2_kernel<<<(CS * TOT / 8) / 1024, 256>>>((const float4*)W2, gamma);
    gb_kernel<<<CS, 256>>>(W2, gamma, beta, b2);
    stats_kernel<<<NROWS / 256, 256>>>();

    gemm2_kernel<<<NROWS / 64, 256, G2_DSMEM>>>(idx);

    finalize_kernel<<<1, 1>>>(out, out_size);
}